// round 15
// baseline (speedup 1.0000x reference)
// R15: BM=256 tile for the large GEMMs (halves B-operand traffic, doubles
// mma-per-issue); qkv3 permanently shelved (implicated in R12/R13 failures).
#include <cuda_runtime.h>
#include <cuda_fp16.h>
#include <math.h>
#include <stdint.h>

// ---------------- problem constants ----------------
#define B_      8
#define S_      1043
#define NPATCH  1024
#define NCLS    19
#define D_      768
#define NH      12
#define DH      64
#define FF      3072
#define GS      32
#define IMG     512
#define M_      (B_*S_)         // 8344
#define BHD     (B_*NH)         // 96
#define MPAD    8576
#define TKV     64
#define NKT     17              // ceil(S_/64)

// ---------------- scratch ----------------------------------------------------
__device__ float g_x[(size_t)M_ * D_];
__device__ __align__(128) __half g_hh[(size_t)MPAD * D_];
#define MDSEG ((size_t)M_ * D_ + 128 * D_)
__device__ __align__(128) __half g_qkvh[3 * MDSEG];   // q | k | v segments
__device__ __align__(128) __half g_ff[(size_t)MPAD * FF];
__device__ float g_patches[(size_t)B_ * NPATCH * D_];
__device__ float g_cls[(size_t)B_ * NCLS * D_];
__device__ float g_mln[(size_t)B_ * NCLS * GS * GS];

#define WTOT 11206656
__device__ __align__(128) __half g_wt[WTOT];
#define OFF_W1_0 0
#define OFF_W1_1 2359296
#define OFF_W2_0 4718592
#define OFF_W2_1 7077888
#define OFF_PD   9437184
#define OFF_PP   10027008
#define OFF_PC   10616832
// per-head transposed qkv weights: [(l*3+m)*12+h] x [e][d] 64x64
__device__ __align__(128) __half g_wqkv[72 * 4096];

// ---------------- helpers ----------------------------------------------------
__device__ __forceinline__ float gelu_exact(float v) {
    return 0.5f * v * (1.f + erff(v * 0.70710678118654752f));
}
__device__ __forceinline__ uint32_t smem_to_u32(const void* p) {
    uint32_t a;
    asm("{ .reg .u64 t; cvta.to.shared.u64 t, %1; cvt.u32.u64 %0, t; }"
        : "=r"(a) : "l"(p));
    return a;
}
__device__ __forceinline__ unsigned packh2(float a, float b) {
    __half2 h = __floats2half2_rn(a, b);
    return *(unsigned*)&h;
}
#define CP16(dst, src) \
    asm volatile("cp.async.cg.shared.global [%0], [%1], 16;" :: "r"(dst), "l"(src))
#define CPCOMMIT() asm volatile("cp.async.commit_group;")
#define CPWAIT0()  asm volatile("cp.async.wait_group 0;")
#define CPWAIT1()  asm volatile("cp.async.wait_group 1;")
#define CPWAIT2()  asm volatile("cp.async.wait_group 2;")

#define HMMA(acc, a0, a1, a2, a3, b0, b1) \
    asm volatile( \
        "mma.sync.aligned.m16n8k16.row.col.f32.f16.f16.f32 " \
        "{%0,%1,%2,%3},{%4,%5,%6,%7},{%8,%9},{%0,%1,%2,%3};" \
        : "+f"((acc)[0]), "+f"((acc)[1]), "+f"((acc)[2]), "+f"((acc)[3]) \
        : "r"(a0), "r"(a1), "r"(a2), "r"(a3), "r"(b0), "r"(b1))

#define LDSM4(r0, r1, r2, r3, addr) \
    asm volatile("ldmatrix.sync.aligned.m8n8.x4.shared.b16 {%0,%1,%2,%3}, [%4];" \
        : "=r"(r0), "=r"(r1), "=r"(r2), "=r"(r3) : "r"(addr))
#define LDSM4T(r0, r1, r2, r3, addr) \
    asm volatile("ldmatrix.sync.aligned.m8n8.x4.trans.shared.b16 {%0,%1,%2,%3}, [%4];" \
        : "=r"(r0), "=r"(r1), "=r"(r2), "=r"(r3) : "r"(addr))

// ---------------- fp16 GEMM, 256x128 tile, 3-stage pipeline ------------------
// C[M,*] = A[M,K] @ B[N,K]^T. 8 warps as 4x2; warp tile 64x64.
// flags: 1 bias, 2 gelu, 4 +=C(fp32), 16 C half.
#define G2_ASTH (256 * 40)
#define G2_BSTH (128 * 40)
#define G2_STH  (G2_ASTH + G2_BSTH)
#define SMEM_G2 (3 * G2_STH * 2)          // 92160 B
__global__ void __launch_bounds__(256) hgemm2(
    const __half* __restrict__ A, const __half* __restrict__ Bm,
    const float* __restrict__ bias, void* __restrict__ Cv,
    int M, int K, int lda, int ldb, int ldc,
    long sA, long sB, long sC, int flags)
{
    extern __shared__ __half smh[];
    const int z = blockIdx.z;
    A  += (long)z * sA;
    Bm += (long)z * sB;

    const int tid = threadIdx.x, warp = tid >> 5, lane = tid & 31;
    const int wm = warp & 3, wn = warp >> 2;     // 4 x 2
    const int l4 = lane >> 2, lm = lane & 3;
    const int m0 = blockIdx.y * 256, n0 = blockIdx.x * 128;
    const uint32_t sb = smem_to_u32(smh);
    const int nch = K >> 5;

    const int arow = (lane & 15), acol8 = (lane >> 4) * 8;
    const int bn_l = ((lane >> 4) & 1) * 8 + (lane & 7);
    const int bc_l = ((lane >> 3) & 1) * 8;

    auto issue = [&](int kc) {
        if (kc < nch) {
            const int st = kc % 3;
            const uint32_t ab = sb + (uint32_t)(st * G2_STH) * 2u;
            const uint32_t bb = ab + (uint32_t)G2_ASTH * 2u;
            const int k0 = kc << 5;
            const __half* Ap = A + (long)m0 * lda + k0;
#pragma unroll
            for (int i = 0; i < 4; i++) {
                int q = i * 256 + tid;
                int row = q >> 2, seg = (q & 3) * 8;
                CP16(ab + (uint32_t)(row * 40 + seg) * 2u,
                     Ap + (long)row * lda + seg);
            }
            const __half* Bp = Bm + (long)n0 * ldb + k0;
#pragma unroll
            for (int i = 0; i < 2; i++) {
                int q = i * 256 + tid;
                int row = q >> 2, seg = (q & 3) * 8;
                CP16(bb + (uint32_t)(row * 40 + seg) * 2u,
                     Bp + (long)row * ldb + seg);
            }
        }
        CPCOMMIT();
    };

    float acc[4][8][4];                    // 4 m-subtiles x 8 n-subtiles
#pragma unroll
    for (int i = 0; i < 4; i++)
#pragma unroll
        for (int j = 0; j < 8; j++)
#pragma unroll
            for (int c = 0; c < 4; c++) acc[i][j][c] = 0.f;

    issue(0); issue(1);

    for (int c = 0; c < nch; c++) {
        CPWAIT1();
        __syncthreads();
        issue(c + 2);

        const uint32_t as = sb + (uint32_t)((c % 3) * G2_STH) * 2u;
        const uint32_t bs = as + (uint32_t)G2_ASTH * 2u;
#pragma unroll
        for (int kk = 0; kk < 32; kk += 16) {
            unsigned af[4][4];
#pragma unroll
            for (int i = 0; i < 4; i++) {
                uint32_t addr = as + (uint32_t)((wm * 64 + i * 16 + arow) * 40
                                                + kk + acol8) * 2u;
                LDSM4(af[i][0], af[i][1], af[i][2], af[i][3], addr);
            }
#pragma unroll
            for (int g = 0; g < 4; g++) {
                unsigned b0, b1, b2, b3;
                uint32_t addr = bs + (uint32_t)((wn * 64 + g * 16 + bn_l) * 40
                                                + kk + bc_l) * 2u;
                LDSM4(b0, b1, b2, b3, addr);
#pragma unroll
                for (int i = 0; i < 4; i++) {
                    HMMA(acc[i][2 * g],     af[i][0], af[i][1], af[i][2], af[i][3], b0, b1);
                    HMMA(acc[i][2 * g + 1], af[i][0], af[i][1], af[i][2], af[i][3], b2, b3);
                }
            }
        }
    }

    float*  Cf = (float*)Cv  + (long)z * sC;
    __half* Ch = (__half*)Cv + (long)z * sC;
#pragma unroll
    for (int i = 0; i < 4; i++)
#pragma unroll
        for (int j = 0; j < 8; j++)
#pragma unroll
            for (int h = 0; h < 2; h++) {
                int row = m0 + wm * 64 + i * 16 + l4 + h * 8;
                if (row >= M) continue;
                int col = n0 + wn * 64 + j * 8 + lm * 2;
                float v0 = acc[i][j][h * 2 + 0];
                float v1 = acc[i][j][h * 2 + 1];
                if (flags & 1) {
                    v0 += bias[col];
                    v1 += bias[col + 1];
                }
                if (flags & 2)  { v0 = gelu_exact(v0); v1 = gelu_exact(v1); }
                if (flags & 16) {
                    *(__half2*)(Ch + (long)row * ldc + col) = __floats2half2_rn(v0, v1);
                } else {
                    float* cp = Cf + (long)row * ldc + col;
                    if (flags & 4) { float2 o = *(float2*)cp; v0 += o.x; v1 += o.y; }
                    float2 st; st.x = v0; st.y = v1;
                    *(float2*)cp = st;
                }
            }
}

// ---------------- fp16 GEMM, 128xBN tile (proj_classes only) -----------------
template<int BN>
__global__ void __launch_bounds__(256) hgemm(
    const __half* __restrict__ A, const __half* __restrict__ Bm,
    const float* __restrict__ bias, void* __restrict__ Cv,
    int M, int Nlim, int K, int lda, int ldb, int ldc,
    int HZ, long sA, long hA, long sB, long hB, long sC, long hC,
    int flags)
{
    constexpr int NT   = BN / 16;
    constexpr int ASTH = 128 * 40;
    constexpr int BSTH = BN * 40;
    constexpr int STH  = ASTH + BSTH;
    extern __shared__ __half smh[];

    const int z = blockIdx.z;
    A  += (long)(z / HZ) * sA + (long)(z % HZ) * hA;
    Bm += (long)(z / HZ) * sB + (long)(z % HZ) * hB;

    const int tid = threadIdx.x, warp = tid >> 5, lane = tid & 31;
    const int wm = warp & 3, wn = warp >> 2;
    const int l4 = lane >> 2, lm = lane & 3;
    const int m0 = blockIdx.y * 128, n0 = blockIdx.x * BN;
    const uint32_t sb = smem_to_u32(smh);
    const int nch = K >> 5;

    const int arow = (lane & 15), acol8 = (lane >> 4) * 8;
    const int bn_l = ((lane >> 4) & 1) * 8 + (lane & 7);
    const int bc_l = ((lane >> 3) & 1) * 8;

    auto issue = [&](int kc) {
        if (kc < nch) {
            const int st = kc & 3;
            const uint32_t ab = sb + (uint32_t)(st * STH) * 2u;
            const uint32_t bb = ab + (uint32_t)ASTH * 2u;
            const int k0 = kc << 5;
            const __half* Ap = A + (long)m0 * lda + k0;
#pragma unroll
            for (int i = 0; i < 2; i++) {
                int q = i * 256 + tid;
                int row = q >> 2, seg = (q & 3) * 8;
                CP16(ab + (uint32_t)(row * 40 + seg) * 2u,
                     Ap + (long)row * lda + seg);
            }
            const __half* Bp = Bm + (long)n0 * ldb + k0;
#pragma unroll
            for (int i = 0; i < BN / 64; i++) {
                int q = i * 256 + tid;
                int row = q >> 2, seg = (q & 3) * 8;
                CP16(bb + (uint32_t)(row * 40 + seg) * 2u,
                     Bp + (long)row * ldb + seg);
            }
        }
        CPCOMMIT();
    };

    float acc[2][NT][4];
#pragma unroll
    for (int i = 0; i < 2; i++)
#pragma unroll
        for (int j = 0; j < NT; j++)
#pragma unroll
            for (int c = 0; c < 4; c++) acc[i][j][c] = 0.f;

    issue(0); issue(1); issue(2);

    for (int c = 0; c < nch; c++) {
        CPWAIT2();
        __syncthreads();
        issue(c + 3);

        const uint32_t as = sb + (uint32_t)((c & 3) * STH) * 2u;
        const uint32_t bs = as + (uint32_t)ASTH * 2u;
#pragma unroll
        for (int kk = 0; kk < 32; kk += 16) {
            unsigned af[2][4];
#pragma unroll
            for (int i = 0; i < 2; i++) {
                uint32_t addr = as + (uint32_t)((wm * 32 + i * 16 + arow) * 40
                                                + kk + acol8) * 2u;
                LDSM4(af[i][0], af[i][1], af[i][2], af[i][3], addr);
            }
#pragma unroll
            for (int g = 0; g < NT / 2; g++) {
                unsigned b0, b1, b2, b3;
                uint32_t addr = bs + (uint32_t)((wn * (BN / 2) + g * 16 + bn_l) * 40
                                                + kk + bc_l) * 2u;
                LDSM4(b0, b1, b2, b3, addr);
#pragma unroll
                for (int i = 0; i < 2; i++) {
                    HMMA(acc[i][2 * g],     af[i][0], af[i][1], af[i][2], af[i][3], b0, b1);
                    HMMA(acc[i][2 * g + 1], af[i][0], af[i][1], af[i][2], af[i][3], b2, b3);
                }
            }
        }
    }

    float*  Cf = (float*)Cv  + (long)(z / HZ) * sC + (long)(z % HZ) * hC;
    __half* Ch = (__half*)Cv + (long)(z / HZ) * sC + (long)(z % HZ) * hC;
#pragma unroll
    for (int i = 0; i < 2; i++)
#pragma unroll
        for (int j = 0; j < NT; j++)
#pragma unroll
            for (int h = 0; h < 2; h++) {
                int row = m0 + wm * 32 + i * 16 + l4 + h * 8;
                if (row >= M) continue;
                int col = n0 + wn * (BN / 2) + j * 8 + lm * 2;
                if (col >= Nlim) continue;
                float v0 = acc[i][j][h * 2 + 0];
                float v1 = acc[i][j][h * 2 + 1];
                bool has1 = (col + 1 < Nlim);
                if (flags & 1) {
                    v0 += bias[col];
                    if (has1) v1 += bias[col + 1];
                }
                if (flags & 2)  { v0 = gelu_exact(v0); v1 = gelu_exact(v1); }
                if (flags & 16) {
                    __half* hp = Ch + (long)row * ldc + col;
                    if (has1) *(__half2*)hp = __floats2half2_rn(v0, v1);
                    else      hp[0] = __float2half_rn(v0);
                } else {
                    float* cp = Cf + (long)row * ldc + col;
                    if (has1) {
                        if (flags & 4) { float2 o = *(float2*)cp; v0 += o.x; v1 += o.y; }
                        float2 st; st.x = v0; st.y = v1;
                        *(float2*)cp = st;
                    } else {
                        if (flags & 4) v0 += cp[0];
                        cp[0] = v0;
                    }
                }
            }
}

// ---------------- fused qkv GEMM (R11-proven): z = m*12+h --------------------
#define QKV_ASTH (128 * 40)
#define QKV_BSTH (64 * 40)
#define QKV_STH  (QKV_ASTH + QKV_BSTH)
__global__ void __launch_bounds__(256) qkv_gemm(
    const __half* __restrict__ A, const __half* __restrict__ Wl,
    const float* __restrict__ qb, const float* __restrict__ kb,
    const float* __restrict__ vb)
{
    extern __shared__ __half smh[];
    const int z = blockIdx.z;
    const int m = z / NH, h = z % NH;
    const __half* Bm = Wl + (long)z * 4096;      // [64 e][64 d]
    const float* bias = (m == 0 ? qb : m == 1 ? kb : vb) + h * DH;
    const float scale = (m == 0) ? 0.125f : 1.f;
    __half* C = g_qkvh + (size_t)m * MDSEG + h * DH;

    const int tid = threadIdx.x, warp = tid >> 5, lane = tid & 31;
    const int wm = warp & 3, wn = warp >> 2;
    const int l4 = lane >> 2, lm = lane & 3;
    const int m0 = blockIdx.y * 128;
    const uint32_t sb = smem_to_u32(smh);

    const int arow = (lane & 15), acol8 = (lane >> 4) * 8;
    const int bn_l = ((lane >> 4) & 1) * 8 + (lane & 7);
    const int bc_l = ((lane >> 3) & 1) * 8;

    auto issue = [&](int kc) {
        if (kc < 2) {
            const int st = kc & 3;
            const uint32_t ab = sb + (uint32_t)(st * QKV_STH) * 2u;
            const uint32_t bb = ab + (uint32_t)QKV_ASTH * 2u;
            const int k0 = kc << 5;
            const __half* Ap = A + (long)m0 * D_ + h * DH + k0;   // head slice
#pragma unroll
            for (int i = 0; i < 2; i++) {
                int q = i * 256 + tid;
                int row = q >> 2, seg = (q & 3) * 8;
                CP16(ab + (uint32_t)(row * 40 + seg) * 2u,
                     Ap + (long)row * D_ + seg);
            }
            {
                int row = tid >> 2, seg = (tid & 3) * 8;
                CP16(bb + (uint32_t)(row * 40 + seg) * 2u,
                     Bm + (long)row * DH + k0 + seg);
            }
        }
        CPCOMMIT();
    };

    float acc[2][4][4];
#pragma unroll
    for (int i = 0; i < 2; i++)
#pragma unroll
        for (int j = 0; j < 4; j++)
#pragma unroll
            for (int c = 0; c < 4; c++) acc[i][j][c] = 0.f;

    issue(0); issue(1); issue(2);

    for (int c = 0; c < 2; c++) {
        CPWAIT2();
        __syncthreads();
        issue(c + 3);
        const uint32_t as = sb + (uint32_t)((c & 3) * QKV_STH) * 2u;
        const uint32_t bs = as + (uint32_t)QKV_ASTH * 2u;
#pragma unroll
        for (int kk = 0; kk < 32; kk += 16) {
            unsigned af[2][4];
#pragma unroll
            for (int i = 0; i < 2; i++) {
                uint32_t addr = as + (uint32_t)((wm * 32 + i * 16 + arow) * 40
                                                + kk + acol8) * 2u;
                LDSM4(af[i][0], af[i][1], af[i][2], af[i][3], addr);
            }
#pragma unroll
            for (int g = 0; g < 2; g++) {
                unsigned b0, b1, b2, b3;
                uint32_t addr = bs + (uint32_t)((wn * 32 + g * 16 + bn_l) * 40
                                                + kk + bc_l) * 2u;
                LDSM4(b0, b1, b2, b3, addr);
#pragma unroll
                for (int i = 0; i < 2; i++) {
                    HMMA(acc[i][2 * g],     af[i][0], af[i][1], af[i][2], af[i][3], b0, b1);
                    HMMA(acc[i][2 * g + 1], af[i][0], af[i][1], af[i][2], af[i][3], b2, b3);
                }
            }
        }
    }

#pragma unroll
    for (int i = 0; i < 2; i++)
#pragma unroll
        for (int j = 0; j < 4; j++)
#pragma unroll
            for (int hh = 0; hh < 2; hh++) {
                int row = m0 + wm * 32 + i * 16 + l4 + hh * 8;
                if (row >= M_) continue;
                int col = wn * 32 + j * 8 + lm * 2;
                float v0 = (acc[i][j][hh * 2 + 0] + bias[col])     * scale;
                float v1 = (acc[i][j][hh * 2 + 1] + bias[col + 1]) * scale;
                *(__half2*)(C + (long)row * D_ + col) = __floats2half2_rn(v0, v1);
            }
}

// ---------------- fused flash attention (V via trans-ldmatrix) --------------
#define FA_QS 0
#define FA_KS (128 * 72)
#define FA_VS (128 * 72 + 2 * 64 * 72)
#define FA_SMEM ((128 * 72 + 4 * 64 * 72) * 2)
__global__ void __launch_bounds__(256) fattn_kernel()
{
    extern __shared__ __half sh[];
    const int z = blockIdx.y;
    const int b = z / NH, hd = z % NH;
    const int m0 = blockIdx.x * 128;
    const int tid = threadIdx.x, warp = tid >> 5, lane = tid & 31;
    const int l4 = lane >> 2, lm = lane & 3;
    const uint32_t sb = smem_to_u32(sh);

    const __half* Qg = g_qkvh + 0 * MDSEG + ((long)b * S_ + m0) * D_ + hd * DH;
    const __half* Kg = g_qkvh + 1 * MDSEG + (long)b * S_ * D_ + hd * DH;
    const __half* Vg = g_qkvh + 2 * MDSEG + (long)b * S_ * D_ + hd * DH;

    const int arow = (lane & 15), acol8 = (lane >> 4) * 8;
    const int bn_l = ((lane >> 4) & 1) * 8 + (lane & 7);
    const int bc_l = ((lane >> 3) & 1) * 8;
    const int tvr = ((lane >> 3) & 1) * 8 + (lane & 7);
    const int tvc = ((lane >> 4) & 1) * 8;

    auto loadKV = [&](int kt) {
        const int st = kt & 1;
        const __half* Kp = Kg + (long)(kt * TKV) * D_;
        const __half* Vp = Vg + (long)(kt * TKV) * D_;
        const uint32_t kb = sb + (uint32_t)(FA_KS + st * 64 * 72) * 2u;
        const uint32_t vb = sb + (uint32_t)(FA_VS + st * 64 * 72) * 2u;
#pragma unroll
        for (int i = 0; i < 2; i++) {
            int q = i * 256 + tid;
            int row = q >> 3, seg = (q & 7) * 8;
            CP16(kb + (uint32_t)(row * 72 + seg) * 2u, Kp + (long)row * D_ + seg);
        }
#pragma unroll
        for (int i = 0; i < 2; i++) {
            int q = i * 256 + tid;
            int row = q >> 3, seg = (q & 7) * 8;
            CP16(vb + (uint32_t)(row * 72 + seg) * 2u, Vp + (long)row * D_ + seg);
        }
    };

#pragma unroll
    for (int i = 0; i < 4; i++) {
        int q = i * 256 + tid;
        int row = q >> 3, seg = (q & 7) * 8;
        CP16(sb + (uint32_t)(FA_QS + row * 72 + seg) * 2u, Qg + (long)row * D_ + seg);
    }
    loadKV(0);
    CPCOMMIT();
    CPWAIT0();
    __syncthreads();

    unsigned qa[4][4];
#pragma unroll
    for (int kc = 0; kc < 4; kc++) {
        uint32_t addr = sb + (uint32_t)(FA_QS + (warp * 16 + arow) * 72
                                        + kc * 16 + acol8) * 2u;
        LDSM4(qa[kc][0], qa[kc][1], qa[kc][2], qa[kc][3], addr);
    }

    float oacc[8][4];
#pragma unroll
    for (int j = 0; j < 8; j++)
#pragma unroll
        for (int c = 0; c < 4; c++) oacc[j][c] = 0.f;
    float mr0 = -1e30f, mr1 = -1e30f, lr0 = 0.f, lr1 = 0.f;

    for (int kt = 0; kt < NKT; kt++) {
        __syncthreads();
        if (kt + 1 < NKT) { loadKV(kt + 1); CPCOMMIT(); CPWAIT1(); }
        else              { CPWAIT0(); }
        __syncthreads();

        const uint32_t ks = sb + (uint32_t)(FA_KS + (kt & 1) * 64 * 72) * 2u;
        const uint32_t vs = sb + (uint32_t)(FA_VS + (kt & 1) * 64 * 72) * 2u;

        float sacc[8][4];
#pragma unroll
        for (int j = 0; j < 8; j++)
#pragma unroll
            for (int c = 0; c < 4; c++) sacc[j][c] = 0.f;
#pragma unroll
        for (int kc = 0; kc < 4; kc++)
#pragma unroll
            for (int g = 0; g < 4; g++) {
                unsigned b0, b1, b2, b3;
                uint32_t addr = ks + (uint32_t)((g * 16 + bn_l) * 72
                                                + kc * 16 + bc_l) * 2u;
                LDSM4(b0, b1, b2, b3, addr);
                HMMA(sacc[2 * g],     qa[kc][0], qa[kc][1], qa[kc][2], qa[kc][3], b0, b1);
                HMMA(sacc[2 * g + 1], qa[kc][0], qa[kc][1], qa[kc][2], qa[kc][3], b2, b3);
            }

        const int base = kt * TKV;
        if (base + TKV > S_) {
#pragma unroll
            for (int j = 0; j < 8; j++) {
                int c0 = base + j * 8 + 2 * lm;
                if (c0 >= S_)     { sacc[j][0] = -1e30f; sacc[j][2] = -1e30f; }
                if (c0 + 1 >= S_) { sacc[j][1] = -1e30f; sacc[j][3] = -1e30f; }
            }
        }

        float tm0 = -1e30f, tm1 = -1e30f;
#pragma unroll
        for (int j = 0; j < 8; j++) {
            tm0 = fmaxf(tm0, fmaxf(sacc[j][0], sacc[j][1]));
            tm1 = fmaxf(tm1, fmaxf(sacc[j][2], sacc[j][3]));
        }
        tm0 = fmaxf(tm0, __shfl_xor_sync(0xffffffff, tm0, 1));
        tm0 = fmaxf(tm0, __shfl_xor_sync(0xffffffff, tm0, 2));
        tm1 = fmaxf(tm1, __shfl_xor_sync(0xffffffff, tm1, 1));
        tm1 = fmaxf(tm1, __shfl_xor_sync(0xffffffff, tm1, 2));
        float mn0 = fmaxf(mr0, tm0), mn1 = fmaxf(mr1, tm1);
        float sc0 = __expf(mr0 - mn0), sc1 = __expf(mr1 - mn1);
        float rs0 = 0.f, rs1 = 0.f;
#pragma unroll
        for (int j = 0; j < 8; j++) {
            sacc[j][0] = __expf(sacc[j][0] - mn0);
            sacc[j][1] = __expf(sacc[j][1] - mn0);
            sacc[j][2] = __expf(sacc[j][2] - mn1);
            sacc[j][3] = __expf(sacc[j][3] - mn1);
            rs0 += sacc[j][0] + sacc[j][1];
            rs1 += sacc[j][2] + sacc[j][3];
        }
        rs0 += __shfl_xor_sync(0xffffffff, rs0, 1);
        rs0 += __shfl_xor_sync(0xffffffff, rs0, 2);
        rs1 += __shfl_xor_sync(0xffffffff, rs1, 1);
        rs1 += __shfl_xor_sync(0xffffffff, rs1, 2);
        lr0 = lr0 * sc0 + rs0;
        lr1 = lr1 * sc1 + rs1;
        mr0 = mn0; mr1 = mn1;
#pragma unroll
        for (int j = 0; j < 8; j++) {
            oacc[j][0] *= sc0; oacc[j][1] *= sc0;
            oacc[j][2] *= sc1; oacc[j][3] *= sc1;
        }

#pragma unroll
        for (int kc2 = 0; kc2 < 4; kc2++) {
            unsigned pa0 = packh2(sacc[2 * kc2][0],     sacc[2 * kc2][1]);
            unsigned pa1 = packh2(sacc[2 * kc2][2],     sacc[2 * kc2][3]);
            unsigned pa2 = packh2(sacc[2 * kc2 + 1][0], sacc[2 * kc2 + 1][1]);
            unsigned pa3 = packh2(sacc[2 * kc2 + 1][2], sacc[2 * kc2 + 1][3]);
#pragma unroll
            for (int g = 0; g < 4; g++) {
                unsigned b0, b1, b2, b3;
                uint32_t addr = vs + (uint32_t)((kc2 * 16 + tvr) * 72
                                                + g * 16 + tvc) * 2u;
                LDSM4T(b0, b1, b2, b3, addr);
                HMMA(oacc[2 * g],     pa0, pa1, pa2, pa3, b0, b1);
                HMMA(oacc[2 * g + 1], pa0, pa1, pa2, pa3, b2, b3);
            }
        }
    }

    const int q0 = m0 + warp * 16 + l4;
    const int q1 = q0 + 8;
    const float inv0 = 1.f / lr0, inv1 = 1.f / lr1;
#pragma unroll
    for (int jd = 0; jd < 8; jd++) {
        int d = hd * DH + jd * 8 + 2 * lm;
        if (q0 < S_) {
            float* p = g_x + ((long)b * S_ + q0) * D_ + d;
            float2 o = *(float2*)p;
            o.x += oacc[jd][0] * inv0;
            o.y += oacc[jd][1] * inv0;
            *(float2*)p = o;
        }
        if (q1 < S_) {
            float* p = g_x + ((long)b * S_ + q1) * D_ + d;
            float2 o = *(float2*)p;
            o.x += oacc[jd][2] * inv1;
            o.y += oacc[jd][3] * inv1;
            *(float2*)p = o;
        }
    }
}

// ---------------- one-shot weight prep (all transposes) ---------------------
__global__ void prep_kernel(
    const float* __restrict__ w1, const float* __restrict__ w2,
    const float* __restrict__ pdW, const float* __restrict__ ppW,
    const float* __restrict__ pcW,
    const float* __restrict__ qW, const float* __restrict__ kW,
    const float* __restrict__ vW)
{
    __shared__ float t[32][33];
    const int bid = blockIdx.x;
    const int tx = threadIdx.x, ty = threadIdx.y;

    if (bid < 10944) {
        const float* src; __half* dst; int K, N, local;
        if (bid < 2304)       { src = w1;                 dst = g_wt + OFF_W1_0; K = 768;  N = 3072; local = bid; }
        else if (bid < 4608)  { src = w1 + (long)D_ * FF; dst = g_wt + OFF_W1_1; K = 768;  N = 3072; local = bid - 2304; }
        else if (bid < 6912)  { src = w2;                 dst = g_wt + OFF_W2_0; K = 3072; N = 768;  local = bid - 4608; }
        else if (bid < 9216)  { src = w2 + (long)FF * D_; dst = g_wt + OFF_W2_1; K = 3072; N = 768;  local = bid - 6912; }
        else if (bid < 9792)  { src = pdW;                dst = g_wt + OFF_PD;   K = 768;  N = 768;  local = bid - 9216; }
        else if (bid < 10368) { src = ppW;                dst = g_wt + OFF_PP;   K = 768;  N = 768;  local = bid - 9792; }
        else                  { src = pcW;                dst = g_wt + OFF_PC;   K = 768;  N = 768;  local = bid - 10368; }
        const int nb = N / 32;
        const int n0 = (local % nb) * 32, k0 = (local / nb) * 32;
#pragma unroll
        for (int i = 0; i < 32; i += 8)
            t[ty + i][tx] = src[(long)(k0 + ty + i) * N + n0 + tx];
        __syncthreads();
#pragma unroll
        for (int i = 0; i < 32; i += 8)
            dst[(long)(n0 + ty + i) * K + k0 + tx] = __float2half_rn(t[tx][ty + i]);
    } else {
        const int local = bid - 10944;           // 0..287
        const int z = local >> 2, tile = local & 3;
        const int l = z / 36, rr = z % 36, m = rr / 12, h = rr % 12;
        const float* src = (m == 0 ? qW : m == 1 ? kW : vW)
                           + ((long)(l * 12 + h) * 64) * 64;
        __half* dst = g_wqkv + (long)z * 4096;
        const int e0 = (tile & 1) * 32, d0 = (tile >> 1) * 32;
#pragma unroll
        for (int i = 0; i < 32; i += 8)
            t[ty + i][tx] = src[(d0 + ty + i) * 64 + e0 + tx];
        __syncthreads();
#pragma unroll
        for (int i = 0; i < 32; i += 8)
            dst[(e0 + ty + i) * 64 + d0 + tx] = __float2half_rn(t[tx][ty + i]);
    }
}

// ---------------- x (fp32) -> g_hh (half) ------------------------------------
__global__ void cvtx_kernel(const float* __restrict__ x)
{
    long i = ((long)blockIdx.x * 256 + threadIdx.x) * 2;
    if (i >= (long)B_ * NPATCH * D_) return;
    float2 v = *(const float2*)(x + i);
    *(__half2*)(g_hh + i) = __floats2half2_rn(v.x, v.y);
}

// ---------------- LayerNorm, warp-per-row, half output only -----------------
__global__ void __launch_bounds__(256) ln_kernel(
    const float* __restrict__ x, const float* __restrict__ g,
    const float* __restrict__ bta, __half* __restrict__ outh)
{
    const int warp = threadIdx.x >> 5, lane = threadIdx.x & 31;
    const long r = (long)blockIdx.x * 8 + warp;
    const float* xr = x + r * D_;
    float v[24];
    float s = 0.f, s2 = 0.f;
#pragma unroll
    for (int i = 0; i < 6; i++) {
        float4 t = *(const float4*)(xr + i * 128 + lane * 4);
        v[i * 4 + 0] = t.x; v[i * 4 + 1] = t.y;
        v[i * 4 + 2] = t.z; v[i * 4 + 3] = t.w;
        s  += t.x + t.y + t.z + t.w;
        s2 += t.x * t.x + t.y * t.y + t.z * t.z + t.w * t.w;
    }
#pragma unroll
    for (int o = 16; o > 0; o >>= 1) {
        s  += __shfl_xor_sync(0xffffffff, s, o);
        s2 += __shfl_xor_sync(0xffffffff, s2, o);
    }
    float mean = s * (1.f / 768.f);
    float var  = s2 * (1.f / 768.f) - mean * mean;
    float inv  = rsqrtf(var + 1e-5f);
    __half* hrow = outh + r * D_;
#pragma unroll
    for (int i = 0; i < 6; i++) {
        int c = i * 128 + lane * 4;
        float4 gg = *(const float4*)(g + c);
        float4 bb = *(const float4*)(bta + c);
        float o0 = (v[i * 4 + 0] - mean) * inv * gg.x + bb.x;
        float o1 = (v[i * 4 + 1] - mean) * inv * gg.y + bb.y;
        float o2 = (v[i * 4 + 2] - mean) * inv * gg.z + bb.z;
        float o3 = (v[i * 4 + 3] - mean) * inv * gg.w + bb.w;
        uint2 st;
        st.x = packh2(o0, o1);
        st.y = packh2(o2, o3);
        *(uint2*)(hrow + c) = st;
    }
}

// ---------------- L2 row normalize (in place), warp-per-row -----------------
__global__ void __launch_bounds__(256) l2norm_kernel(float* __restrict__ x)
{
    const int warp = threadIdx.x >> 5, lane = threadIdx.x & 31;
    const long r = (long)blockIdx.x * 8 + warp;
    float* xr = x + r * D_;
    float v[24];
    float s2 = 0.f;
#pragma unroll
    for (int i = 0; i < 6; i++) {
        float4 t = *(const float4*)(xr + i * 128 + lane * 4);
        v[i * 4 + 0] = t.x; v[i * 4 + 1] = t.y;
        v[i * 4 + 2] = t.z; v[i * 4 + 3] = t.w;
        s2 += t.x * t.x + t.y * t.y + t.z * t.z + t.w * t.w;
    }
#pragma unroll
    for (int o = 16; o > 0; o >>= 1)
        s2 += __shfl_xor_sync(0xffffffff, s2, o);
    float inv = rsqrtf(s2);
#pragma unroll
    for (int i = 0; i < 6; i++) {
        float4 t;
        t.x = v[i * 4 + 0] * inv; t.y = v[i * 4 + 1] * inv;
        t.z = v[i * 4 + 2] * inv; t.w = v[i * 4 + 3] * inv;
        *(float4*)(xr + i * 128 + lane * 4) = t;
    }
}

// ---------------- broadcast cls_emb into g_x cls rows -----------------------
__global__ void fill_cls_kernel(const float* __restrict__ cls_emb)
{
    int idx = blockIdx.x * 256 + threadIdx.x;
    if (idx >= NCLS * D_) return;
    float v = cls_emb[idx];
    int c = idx / D_, d = idx % D_;
#pragma unroll
    for (int b = 0; b < B_; b++)
        g_x[(long)(b * S_ + NPATCH + c) * D_ + d] = v;
}

// ---------------- masks + mask-LN fused -------------------------------------
__global__ void __launch_bounds__(256) masks_kernel(
    const float* __restrict__ mg, const float* __restrict__ mb)
{
    __shared__ float pt[64][128];
    __shared__ float cs[NCLS][128];
    __shared__ float sm_m[64][20];
    const int b = blockIdx.y;
    const int t0 = blockIdx.x * 64;
    const int tid = threadIdx.x;
    float acc[5];
#pragma unroll
    for (int i = 0; i < 5; i++) acc[i] = 0.f;

    for (int d0 = 0; d0 < D_; d0 += 128) {
#pragma unroll
        for (int i = 0; i < 8; i++) {
            int f = i * 256 + tid;
            int row = f >> 5, c4 = (f & 31) * 4;
            *(float4*)&pt[row][c4] =
                *(const float4*)(g_patches + (long)(b * NPATCH + t0 + row) * D_ + d0 + c4);
        }
        for (int f = tid; f < NCLS * 32; f += 256) {
            int row = f >> 5, c4 = (f & 31) * 4;
            *(float4*)&cs[row][c4] =
                *(const float4*)(g_cls + (long)(b * NCLS + row) * D_ + d0 + c4);
        }
        __syncthreads();
#pragma unroll
        for (int i = 0; i < 5; i++) {
            int p = i * 256 + tid;
            if (p < 64 * NCLS) {
                int tok = p / NCLS, c = p % NCLS;
                float s = acc[i];
#pragma unroll 8
                for (int d = 0; d < 128; d++)
                    s = fmaf(pt[tok][d], cs[c][d], s);
                acc[i] = s;
            }
        }
        __syncthreads();
    }
#pragma unroll
    for (int i = 0; i < 5; i++) {
        int p = i * 256 + tid;
        if (p < 64 * NCLS) sm_m[p / NCLS][p % NCLS] = acc[i];
    }
    __syncthreads();

    if (tid < 64) {
        const int n = t0 + tid;
        float mean = 0.f;
#pragma unroll
        for (int c = 0; c < NCLS; c++) mean += sm_m[tid][c];
        mean *= (1.f / (float)NCLS);
        float var = 0.f;
#pragma unroll
        for (int c = 0; c < NCLS; c++) {
            float d = sm_m[tid][c] - mean;
            var += d * d;
        }
        var *= (1.f / (float)NCLS);
        float inv = rsqrtf(var + 1e-5f);
        const int gy = n >> 5, gx = n & 31;
#pragma unroll
        for (int c = 0; c < NCLS; c++)
            g_mln[(((long)b * NCLS + c) * GS + gy) * GS + gx] =
                (sm_m[tid][c] - mean) * inv * mg[c] + mb[c];
    }
}

// ---------------- bilinear 32x32 -> 512x512 ---------------------------------
__global__ void __launch_bounds__(256) resize_kernel(float* __restrict__ out)
{
    const int pix = blockIdx.x * 256 + threadIdx.x;
    const int c = blockIdx.y, b = blockIdx.z;
    const int ox = pix & 511, oy = pix >> 9;
    float fx = (ox + 0.5f) * 0.0625f - 0.5f;
    float fy = (oy + 0.5f) * 0.0625f - 0.5f;
    int ix0 = (int)floorf(fx), iy0 = (int)floorf(fy);
    float wx = fx - (float)ix0, wy = fy - (float)iy0;
    int x0 = max(ix0, 0), x1 = min(ix0 + 1, GS - 1);
    int y0 = max(iy0, 0), y1 = min(iy0 + 1, GS - 1);
    const float* m = g_mln + ((long)b * NCLS + c) * GS * GS;
    float v00 = m[y0 * GS + x0], v01 = m[y0 * GS + x1];
    float v10 = m[y1 * GS + x0], v11 = m[y1 * GS + x1];
    float v = (1.f - wy) * ((1.f - wx) * v00 + wx * v01)
            +        wy  * ((1.f - wx) * v10 + wx * v11);
    out[(((long)b * NCLS + c) * IMG + oy) * IMG + ox] = v;
}

// ---------------- host orchestration ----------------------------------------
static void* sym_addr(const void* sym)
{
    void* p = nullptr;
    cudaGetSymbolAddress(&p, sym);
    return p;
}

#define SMEM_H128 ((128 * 40 + 128 * 40) * 2 * 4)   // 81920
#define SMEM_QKV  ((128 * 40 + 64 * 40) * 2 * 4)    // 61440

extern "C" void kernel_launch(void* const* d_in, const int* in_sizes, int n_in,
                              void* d_out, int out_size)
{
    (void)in_sizes; (void)n_in; (void)out_size;
    const float* x    = (const float*)d_in[0];
    const float* pdW  = (const float*)d_in[1];
    const float* pdb  = (const float*)d_in[2];
    const float* cls  = (const float*)d_in[3];
    const float* l1g  = (const float*)d_in[4];
    const float* l1b  = (const float*)d_in[5];
    const float* qW   = (const float*)d_in[6];
    const float* qb   = (const float*)d_in[7];
    const float* kW   = (const float*)d_in[8];
    const float* kb   = (const float*)d_in[9];
    const float* vW   = (const float*)d_in[10];
    const float* vb   = (const float*)d_in[11];
    const float* l2g  = (const float*)d_in[12];
    const float* l2b  = (const float*)d_in[13];
    const float* w1   = (const float*)d_in[14];
    const float* b1   = (const float*)d_in[15];
    const float* w2   = (const float*)d_in[16];
    const float* b2   = (const float*)d_in[17];
    const float* ppW  = (const float*)d_in[18];
    const float* pcW  = (const float*)d_in[19];
    const float* dg   = (const float*)d_in[20];
    const float* db   = (const float*)d_in[21];
    const float* mg   = (const float*)d_in[22];
    const float* mb   = (const float*)d_in[23];
    float* out = (float*)d_out;

    float*  gx   = (float*)sym_addr(g_x);
    __half* ghh  = (__half*)sym_addr(g_hh);
    __half* gff  = (__half*)sym_addr(g_ff);
    float*  gpt  = (float*)sym_addr(g_patches);
    float*  gcl  = (float*)sym_addr(g_cls);
    __half* wt   = (__half*)sym_addr(g_wt);
    __half* wqkv = (__half*)sym_addr(g_wqkv);

    cudaFuncSetAttribute(hgemm2,
                         cudaFuncAttributeMaxDynamicSharedMemorySize, SMEM_G2);
    cudaFuncSetAttribute(hgemm<128>,
                         cudaFuncAttributeMaxDynamicSharedMemorySize, SMEM_H128);
    cudaFuncSetAttribute(qkv_gemm,
                         cudaFuncAttributeMaxDynamicSharedMemorySize, SMEM_QKV);
    cudaFuncSetAttribute(fattn_kernel,
                         cudaFuncAttributeMaxDynamicSharedMemorySize, FA_SMEM);

    const dim3 blk(256);
    const dim3 tsb(32, 8);
    const int mtiles  = (M_ + 127) / 128;     // 66
    const int mtiles2 = (M_ + 255) / 256;     // 33

    // ---- one-shot prep: all weight transposes + x->half ----
    prep_kernel<<<11232, tsb>>>(w1, w2, pdW, ppW, pcW, qW, kW, vW);
    cvtx_kernel<<<(B_ * NPATCH * D_ / 2 + 255) / 256, 256>>>(x);

    // ---- x(half) @ proj_dec + b -> g_x (batched: 8 x [1024,768]) ----
    hgemm2<<<dim3(6, 4, B_), blk, SMEM_G2>>>(
        ghh, wt + OFF_PD, pdb, gx,
        NPATCH, D_, D_, D_, D_,
        (long)NPATCH * D_, 0, (long)S_ * D_, 1);
    fill_cls_kernel<<<(NCLS * D_ + 255) / 256, 256>>>(cls);

    for (int l = 0; l < 2; l++) {
        ln_kernel<<<M_ / 8, blk>>>(gx, l1g + l * D_, l1b + l * D_, ghh);

        qkv_gemm<<<dim3(1, mtiles, 36), blk, SMEM_QKV>>>(
            ghh, wqkv + (long)l * 36 * 4096,
            qb + (long)l * NH * DH, kb + (long)l * NH * DH, vb + (long)l * NH * DH);

        fattn_kernel<<<dim3((S_ + 127) / 128, BHD), blk, FA_SMEM>>>();

        ln_kernel<<<M_ / 8, blk>>>(gx, l2g + l * D_, l2b + l * D_, ghh);

        hgemm2<<<dim3(FF / 128, mtiles2, 1), blk, SMEM_G2>>>(
            ghh, wt + (l ? OFF_W1_1 : OFF_W1_0), b1 + (long)l * FF, gff,
            M_, D_, D_, D_, FF, 0, 0, 0, 1 | 2 | 16);
        hgemm2<<<dim3(D_ / 128, mtiles2, 1), blk, SMEM_G2>>>(
            gff, wt + (l ? OFF_W2_1 : OFF_W2_0), b2 + (long)l * D_, gx,
            M_, FF, FF, FF, D_, 0, 0, 0, 1 | 4);
    }

    ln_kernel<<<M_ / 8, blk>>>(gx, dg, db, ghh);

    hgemm2<<<dim3(6, 4, B_), blk, SMEM_G2>>>(
        ghh, wt + OFF_PP, nullptr, gpt,
        NPATCH, D_, D_, D_, D_,
        (long)S_ * D_, 0, (long)NPATCH * D_, 0);
    hgemm<128><<<dim3(6, 1, B_), blk, SMEM_H128>>>(
        ghh + (long)NPATCH * D_, wt + OFF_PC, nullptr, gcl,
        NCLS, D_, D_, D_, D_, D_,
        1, (long)S_ * D_, 0, 0, 0, (long)NCLS * D_, 0, 0);

    l2norm_kernel<<<B_ * NPATCH / 8, blk>>>(gpt);
    l2norm_kernel<<<B_ * NCLS / 8, blk>>>(gcl);

    masks_kernel<<<dim3(NPATCH / 64, B_), blk>>>(mg, mb);
    resize_kernel<<<dim3(IMG * IMG / 256, NCLS, B_), blk>>>(out);
}

// round 16
// speedup vs baseline: 1.2543x; 1.2543x over previous
// R16: revert BM=256 regression to R14's proven 128x128 hgemm; fold fill_cls
// into cvtx and merge the two l2norm launches (launch-tail skim).
#include <cuda_runtime.h>
#include <cuda_fp16.h>
#include <math.h>
#include <stdint.h>

// ---------------- problem constants ----------------
#define B_      8
#define S_      1043
#define NPATCH  1024
#define NCLS    19
#define D_      768
#define NH      12
#define DH      64
#define FF      3072
#define GS      32
#define IMG     512
#define M_      (B_*S_)         // 8344
#define BHD     (B_*NH)         // 96
#define MPAD    8576
#define TKV     64
#define NKT     17              // ceil(S_/64)

// ---------------- scratch ----------------------------------------------------
__device__ float g_x[(size_t)M_ * D_];
__device__ __align__(128) __half g_hh[(size_t)MPAD * D_];
#define MDSEG ((size_t)M_ * D_ + 128 * D_)
__device__ __align__(128) __half g_qkvh[3 * MDSEG];   // q | k | v segments
__device__ __align__(128) __half g_ff[(size_t)MPAD * FF];
__device__ float g_patches[(size_t)B_ * NPATCH * D_];
__device__ float g_cls[(size_t)B_ * NCLS * D_ + 40 * D_];  // slack for merged l2norm tail
__device__ float g_mln[(size_t)B_ * NCLS * GS * GS];

#define WTOT 11206656
__device__ __align__(128) __half g_wt[WTOT];
#define OFF_W1_0 0
#define OFF_W1_1 2359296
#define OFF_W2_0 4718592
#define OFF_W2_1 7077888
#define OFF_PD   9437184
#define OFF_PP   10027008
#define OFF_PC   10616832
// per-head transposed qkv weights: [(l*3+m)*12+h] x [e][d] 64x64
__device__ __align__(128) __half g_wqkv[72 * 4096];

// ---------------- helpers ----------------------------------------------------
__device__ __forceinline__ float gelu_exact(float v) {
    return 0.5f * v * (1.f + erff(v * 0.70710678118654752f));
}
__device__ __forceinline__ uint32_t smem_to_u32(const void* p) {
    uint32_t a;
    asm("{ .reg .u64 t; cvta.to.shared.u64 t, %1; cvt.u32.u64 %0, t; }"
        : "=r"(a) : "l"(p));
    return a;
}
__device__ __forceinline__ unsigned packh2(float a, float b) {
    __half2 h = __floats2half2_rn(a, b);
    return *(unsigned*)&h;
}
#define CP16(dst, src) \
    asm volatile("cp.async.cg.shared.global [%0], [%1], 16;" :: "r"(dst), "l"(src))
#define CPCOMMIT() asm volatile("cp.async.commit_group;")
#define CPWAIT0()  asm volatile("cp.async.wait_group 0;")
#define CPWAIT1()  asm volatile("cp.async.wait_group 1;")
#define CPWAIT2()  asm volatile("cp.async.wait_group 2;")

#define HMMA(acc, a0, a1, a2, a3, b0, b1) \
    asm volatile( \
        "mma.sync.aligned.m16n8k16.row.col.f32.f16.f16.f32 " \
        "{%0,%1,%2,%3},{%4,%5,%6,%7},{%8,%9},{%0,%1,%2,%3};" \
        : "+f"((acc)[0]), "+f"((acc)[1]), "+f"((acc)[2]), "+f"((acc)[3]) \
        : "r"(a0), "r"(a1), "r"(a2), "r"(a3), "r"(b0), "r"(b1))

#define LDSM4(r0, r1, r2, r3, addr) \
    asm volatile("ldmatrix.sync.aligned.m8n8.x4.shared.b16 {%0,%1,%2,%3}, [%4];" \
        : "=r"(r0), "=r"(r1), "=r"(r2), "=r"(r3) : "r"(addr))
#define LDSM4T(r0, r1, r2, r3, addr) \
    asm volatile("ldmatrix.sync.aligned.m8n8.x4.trans.shared.b16 {%0,%1,%2,%3}, [%4];" \
        : "=r"(r0), "=r"(r1), "=r"(r2), "=r"(r3) : "r"(addr))

// ---------------- fp16 tensor-core GEMM (128xBN tile, R14-proven) ------------
// C[M,*] = A[M,K] @ B[N,K]^T. flags: 1 bias, 2 gelu, 4 +=C(fp32), 16 C half.
template<int BN>
__global__ void __launch_bounds__(256) hgemm(
    const __half* __restrict__ A, const __half* __restrict__ Bm,
    const float* __restrict__ bias, void* __restrict__ Cv,
    int M, int Nlim, int K, int lda, int ldb, int ldc,
    int HZ, long sA, long hA, long sB, long hB, long sC, long hC,
    int flags)
{
    constexpr int NT   = BN / 16;
    constexpr int ASTH = 128 * 40;
    constexpr int BSTH = BN * 40;
    constexpr int STH  = ASTH + BSTH;
    extern __shared__ __half smh[];

    const int z = blockIdx.z;
    A  += (long)(z / HZ) * sA + (long)(z % HZ) * hA;
    Bm += (long)(z / HZ) * sB + (long)(z % HZ) * hB;

    const int tid = threadIdx.x, warp = tid >> 5, lane = tid & 31;
    const int wm = warp & 3, wn = warp >> 2;
    const int l4 = lane >> 2, lm = lane & 3;
    const int m0 = blockIdx.y * 128, n0 = blockIdx.x * BN;
    const uint32_t sb = smem_to_u32(smh);
    const int nch = K >> 5;

    const int arow = (lane & 15), acol8 = (lane >> 4) * 8;
    const int bn_l = ((lane >> 4) & 1) * 8 + (lane & 7);
    const int bc_l = ((lane >> 3) & 1) * 8;

    auto issue = [&](int kc) {
        if (kc < nch) {
            const int st = kc & 3;
            const uint32_t ab = sb + (uint32_t)(st * STH) * 2u;
            const uint32_t bb = ab + (uint32_t)ASTH * 2u;
            const int k0 = kc << 5;
            const __half* Ap = A + (long)m0 * lda + k0;
#pragma unroll
            for (int i = 0; i < 2; i++) {
                int q = i * 256 + tid;
                int row = q >> 2, seg = (q & 3) * 8;
                CP16(ab + (uint32_t)(row * 40 + seg) * 2u,
                     Ap + (long)row * lda + seg);
            }
            const __half* Bp = Bm + (long)n0 * ldb + k0;
#pragma unroll
            for (int i = 0; i < BN / 64; i++) {
                int q = i * 256 + tid;
                int row = q >> 2, seg = (q & 3) * 8;
                CP16(bb + (uint32_t)(row * 40 + seg) * 2u,
                     Bp + (long)row * ldb + seg);
            }
        }
        CPCOMMIT();
    };

    float acc[2][NT][4];
#pragma unroll
    for (int i = 0; i < 2; i++)
#pragma unroll
        for (int j = 0; j < NT; j++)
#pragma unroll
            for (int c = 0; c < 4; c++) acc[i][j][c] = 0.f;

    issue(0); issue(1); issue(2);

    for (int c = 0; c < nch; c++) {
        CPWAIT2();
        __syncthreads();
        issue(c + 3);

        const uint32_t as = sb + (uint32_t)((c & 3) * STH) * 2u;
        const uint32_t bs = as + (uint32_t)ASTH * 2u;
#pragma unroll
        for (int kk = 0; kk < 32; kk += 16) {
            unsigned af[2][4];
#pragma unroll
            for (int i = 0; i < 2; i++) {
                uint32_t addr = as + (uint32_t)((wm * 32 + i * 16 + arow) * 40
                                                + kk + acol8) * 2u;
                LDSM4(af[i][0], af[i][1], af[i][2], af[i][3], addr);
            }
#pragma unroll
            for (int g = 0; g < NT / 2; g++) {
                unsigned b0, b1, b2, b3;
                uint32_t addr = bs + (uint32_t)((wn * (BN / 2) + g * 16 + bn_l) * 40
                                                + kk + bc_l) * 2u;
                LDSM4(b0, b1, b2, b3, addr);
#pragma unroll
                for (int i = 0; i < 2; i++) {
                    HMMA(acc[i][2 * g],     af[i][0], af[i][1], af[i][2], af[i][3], b0, b1);
                    HMMA(acc[i][2 * g + 1], af[i][0], af[i][1], af[i][2], af[i][3], b2, b3);
                }
            }
        }
    }

    float*  Cf = (float*)Cv  + (long)(z / HZ) * sC + (long)(z % HZ) * hC;
    __half* Ch = (__half*)Cv + (long)(z / HZ) * sC + (long)(z % HZ) * hC;
#pragma unroll
    for (int i = 0; i < 2; i++)
#pragma unroll
        for (int j = 0; j < NT; j++)
#pragma unroll
            for (int h = 0; h < 2; h++) {
                int row = m0 + wm * 32 + i * 16 + l4 + h * 8;
                if (row >= M) continue;
                int col = n0 + wn * (BN / 2) + j * 8 + lm * 2;
                if (col >= Nlim) continue;
                float v0 = acc[i][j][h * 2 + 0];
                float v1 = acc[i][j][h * 2 + 1];
                bool has1 = (col + 1 < Nlim);
                if (flags & 1) {
                    v0 += bias[col];
                    if (has1) v1 += bias[col + 1];
                }
                if (flags & 2)  { v0 = gelu_exact(v0); v1 = gelu_exact(v1); }
                if (flags & 16) {
                    __half* hp = Ch + (long)row * ldc + col;
                    if (has1) *(__half2*)hp = __floats2half2_rn(v0, v1);
                    else      hp[0] = __float2half_rn(v0);
                } else {
                    float* cp = Cf + (long)row * ldc + col;
                    if (has1) {
                        if (flags & 4) { float2 o = *(float2*)cp; v0 += o.x; v1 += o.y; }
                        float2 st; st.x = v0; st.y = v1;
                        *(float2*)cp = st;
                    } else {
                        if (flags & 4) v0 += cp[0];
                        cp[0] = v0;
                    }
                }
            }
}

// ---------------- fused qkv GEMM (R11-proven): z = m*12+h --------------------
#define QKV_ASTH (128 * 40)
#define QKV_BSTH (64 * 40)
#define QKV_STH  (QKV_ASTH + QKV_BSTH)
__global__ void __launch_bounds__(256) qkv_gemm(
    const __half* __restrict__ A, const __half* __restrict__ Wl,
    const float* __restrict__ qb, const float* __restrict__ kb,
    const float* __restrict__ vb)
{
    extern __shared__ __half smh[];
    const int z = blockIdx.z;
    const int m = z / NH, h = z % NH;
    const __half* Bm = Wl + (long)z * 4096;      // [64 e][64 d]
    const float* bias = (m == 0 ? qb : m == 1 ? kb : vb) + h * DH;
    const float scale = (m == 0) ? 0.125f : 1.f;
    __half* C = g_qkvh + (size_t)m * MDSEG + h * DH;

    const int tid = threadIdx.x, warp = tid >> 5, lane = tid & 31;
    const int wm = warp & 3, wn = warp >> 2;
    const int l4 = lane >> 2, lm = lane & 3;
    const int m0 = blockIdx.y * 128;
    const uint32_t sb = smem_to_u32(smh);

    const int arow = (lane & 15), acol8 = (lane >> 4) * 8;
    const int bn_l = ((lane >> 4) & 1) * 8 + (lane & 7);
    const int bc_l = ((lane >> 3) & 1) * 8;

    auto issue = [&](int kc) {
        if (kc < 2) {
            const int st = kc & 3;
            const uint32_t ab = sb + (uint32_t)(st * QKV_STH) * 2u;
            const uint32_t bb = ab + (uint32_t)QKV_ASTH * 2u;
            const int k0 = kc << 5;
            const __half* Ap = A + (long)m0 * D_ + h * DH + k0;   // head slice
#pragma unroll
            for (int i = 0; i < 2; i++) {
                int q = i * 256 + tid;
                int row = q >> 2, seg = (q & 3) * 8;
                CP16(ab + (uint32_t)(row * 40 + seg) * 2u,
                     Ap + (long)row * D_ + seg);
            }
            {
                int row = tid >> 2, seg = (tid & 3) * 8;
                CP16(bb + (uint32_t)(row * 40 + seg) * 2u,
                     Bm + (long)row * DH + k0 + seg);
            }
        }
        CPCOMMIT();
    };

    float acc[2][4][4];
#pragma unroll
    for (int i = 0; i < 2; i++)
#pragma unroll
        for (int j = 0; j < 4; j++)
#pragma unroll
            for (int c = 0; c < 4; c++) acc[i][j][c] = 0.f;

    issue(0); issue(1); issue(2);

    for (int c = 0; c < 2; c++) {
        CPWAIT2();
        __syncthreads();
        issue(c + 3);
        const uint32_t as = sb + (uint32_t)((c & 3) * QKV_STH) * 2u;
        const uint32_t bs = as + (uint32_t)QKV_ASTH * 2u;
#pragma unroll
        for (int kk = 0; kk < 32; kk += 16) {
            unsigned af[2][4];
#pragma unroll
            for (int i = 0; i < 2; i++) {
                uint32_t addr = as + (uint32_t)((wm * 32 + i * 16 + arow) * 40
                                                + kk + acol8) * 2u;
                LDSM4(af[i][0], af[i][1], af[i][2], af[i][3], addr);
            }
#pragma unroll
            for (int g = 0; g < 2; g++) {
                unsigned b0, b1, b2, b3;
                uint32_t addr = bs + (uint32_t)((wn * 32 + g * 16 + bn_l) * 40
                                                + kk + bc_l) * 2u;
                LDSM4(b0, b1, b2, b3, addr);
#pragma unroll
                for (int i = 0; i < 2; i++) {
                    HMMA(acc[i][2 * g],     af[i][0], af[i][1], af[i][2], af[i][3], b0, b1);
                    HMMA(acc[i][2 * g + 1], af[i][0], af[i][1], af[i][2], af[i][3], b2, b3);
                }
            }
        }
    }

#pragma unroll
    for (int i = 0; i < 2; i++)
#pragma unroll
        for (int j = 0; j < 4; j++)
#pragma unroll
            for (int hh = 0; hh < 2; hh++) {
                int row = m0 + wm * 32 + i * 16 + l4 + hh * 8;
                if (row >= M_) continue;
                int col = wn * 32 + j * 8 + lm * 2;
                float v0 = (acc[i][j][hh * 2 + 0] + bias[col])     * scale;
                float v1 = (acc[i][j][hh * 2 + 1] + bias[col + 1]) * scale;
                *(__half2*)(C + (long)row * D_ + col) = __floats2half2_rn(v0, v1);
            }
}

// ---------------- fused flash attention (V via trans-ldmatrix) --------------
#define FA_QS 0
#define FA_KS (128 * 72)
#define FA_VS (128 * 72 + 2 * 64 * 72)
#define FA_SMEM ((128 * 72 + 4 * 64 * 72) * 2)
__global__ void __launch_bounds__(256) fattn_kernel()
{
    extern __shared__ __half sh[];
    const int z = blockIdx.y;
    const int b = z / NH, hd = z % NH;
    const int m0 = blockIdx.x * 128;
    const int tid = threadIdx.x, warp = tid >> 5, lane = tid & 31;
    const int l4 = lane >> 2, lm = lane & 3;
    const uint32_t sb = smem_to_u32(sh);

    const __half* Qg = g_qkvh + 0 * MDSEG + ((long)b * S_ + m0) * D_ + hd * DH;
    const __half* Kg = g_qkvh + 1 * MDSEG + (long)b * S_ * D_ + hd * DH;
    const __half* Vg = g_qkvh + 2 * MDSEG + (long)b * S_ * D_ + hd * DH;

    const int arow = (lane & 15), acol8 = (lane >> 4) * 8;
    const int bn_l = ((lane >> 4) & 1) * 8 + (lane & 7);
    const int bc_l = ((lane >> 3) & 1) * 8;
    const int tvr = ((lane >> 3) & 1) * 8 + (lane & 7);
    const int tvc = ((lane >> 4) & 1) * 8;

    auto loadKV = [&](int kt) {
        const int st = kt & 1;
        const __half* Kp = Kg + (long)(kt * TKV) * D_;
        const __half* Vp = Vg + (long)(kt * TKV) * D_;
        const uint32_t kb = sb + (uint32_t)(FA_KS + st * 64 * 72) * 2u;
        const uint32_t vb = sb + (uint32_t)(FA_VS + st * 64 * 72) * 2u;
#pragma unroll
        for (int i = 0; i < 2; i++) {
            int q = i * 256 + tid;
            int row = q >> 3, seg = (q & 7) * 8;
            CP16(kb + (uint32_t)(row * 72 + seg) * 2u, Kp + (long)row * D_ + seg);
        }
#pragma unroll
        for (int i = 0; i < 2; i++) {
            int q = i * 256 + tid;
            int row = q >> 3, seg = (q & 7) * 8;
            CP16(vb + (uint32_t)(row * 72 + seg) * 2u, Vp + (long)row * D_ + seg);
        }
    };

#pragma unroll
    for (int i = 0; i < 4; i++) {
        int q = i * 256 + tid;
        int row = q >> 3, seg = (q & 7) * 8;
        CP16(sb + (uint32_t)(FA_QS + row * 72 + seg) * 2u, Qg + (long)row * D_ + seg);
    }
    loadKV(0);
    CPCOMMIT();
    CPWAIT0();
    __syncthreads();

    unsigned qa[4][4];
#pragma unroll
    for (int kc = 0; kc < 4; kc++) {
        uint32_t addr = sb + (uint32_t)(FA_QS + (warp * 16 + arow) * 72
                                        + kc * 16 + acol8) * 2u;
        LDSM4(qa[kc][0], qa[kc][1], qa[kc][2], qa[kc][3], addr);
    }

    float oacc[8][4];
#pragma unroll
    for (int j = 0; j < 8; j++)
#pragma unroll
        for (int c = 0; c < 4; c++) oacc[j][c] = 0.f;
    float mr0 = -1e30f, mr1 = -1e30f, lr0 = 0.f, lr1 = 0.f;

    for (int kt = 0; kt < NKT; kt++) {
        __syncthreads();
        if (kt + 1 < NKT) { loadKV(kt + 1); CPCOMMIT(); CPWAIT1(); }
        else              { CPWAIT0(); }
        __syncthreads();

        const uint32_t ks = sb + (uint32_t)(FA_KS + (kt & 1) * 64 * 72) * 2u;
        const uint32_t vs = sb + (uint32_t)(FA_VS + (kt & 1) * 64 * 72) * 2u;

        float sacc[8][4];
#pragma unroll
        for (int j = 0; j < 8; j++)
#pragma unroll
            for (int c = 0; c < 4; c++) sacc[j][c] = 0.f;
#pragma unroll
        for (int kc = 0; kc < 4; kc++)
#pragma unroll
            for (int g = 0; g < 4; g++) {
                unsigned b0, b1, b2, b3;
                uint32_t addr = ks + (uint32_t)((g * 16 + bn_l) * 72
                                                + kc * 16 + bc_l) * 2u;
                LDSM4(b0, b1, b2, b3, addr);
                HMMA(sacc[2 * g],     qa[kc][0], qa[kc][1], qa[kc][2], qa[kc][3], b0, b1);
                HMMA(sacc[2 * g + 1], qa[kc][0], qa[kc][1], qa[kc][2], qa[kc][3], b2, b3);
            }

        const int base = kt * TKV;
        if (base + TKV > S_) {
#pragma unroll
            for (int j = 0; j < 8; j++) {
                int c0 = base + j * 8 + 2 * lm;
                if (c0 >= S_)     { sacc[j][0] = -1e30f; sacc[j][2] = -1e30f; }
                if (c0 + 1 >= S_) { sacc[j][1] = -1e30f; sacc[j][3] = -1e30f; }
            }
        }

        float tm0 = -1e30f, tm1 = -1e30f;
#pragma unroll
        for (int j = 0; j < 8; j++) {
            tm0 = fmaxf(tm0, fmaxf(sacc[j][0], sacc[j][1]));
            tm1 = fmaxf(tm1, fmaxf(sacc[j][2], sacc[j][3]));
        }
        tm0 = fmaxf(tm0, __shfl_xor_sync(0xffffffff, tm0, 1));
        tm0 = fmaxf(tm0, __shfl_xor_sync(0xffffffff, tm0, 2));
        tm1 = fmaxf(tm1, __shfl_xor_sync(0xffffffff, tm1, 1));
        tm1 = fmaxf(tm1, __shfl_xor_sync(0xffffffff, tm1, 2));
        float mn0 = fmaxf(mr0, tm0), mn1 = fmaxf(mr1, tm1);
        float sc0 = __expf(mr0 - mn0), sc1 = __expf(mr1 - mn1);
        float rs0 = 0.f, rs1 = 0.f;
#pragma unroll
        for (int j = 0; j < 8; j++) {
            sacc[j][0] = __expf(sacc[j][0] - mn0);
            sacc[j][1] = __expf(sacc[j][1] - mn0);
            sacc[j][2] = __expf(sacc[j][2] - mn1);
            sacc[j][3] = __expf(sacc[j][3] - mn1);
            rs0 += sacc[j][0] + sacc[j][1];
            rs1 += sacc[j][2] + sacc[j][3];
        }
        rs0 += __shfl_xor_sync(0xffffffff, rs0, 1);
        rs0 += __shfl_xor_sync(0xffffffff, rs0, 2);
        rs1 += __shfl_xor_sync(0xffffffff, rs1, 1);
        rs1 += __shfl_xor_sync(0xffffffff, rs1, 2);
        lr0 = lr0 * sc0 + rs0;
        lr1 = lr1 * sc1 + rs1;
        mr0 = mn0; mr1 = mn1;
#pragma unroll
        for (int j = 0; j < 8; j++) {
            oacc[j][0] *= sc0; oacc[j][1] *= sc0;
            oacc[j][2] *= sc1; oacc[j][3] *= sc1;
        }

#pragma unroll
        for (int kc2 = 0; kc2 < 4; kc2++) {
            unsigned pa0 = packh2(sacc[2 * kc2][0],     sacc[2 * kc2][1]);
            unsigned pa1 = packh2(sacc[2 * kc2][2],     sacc[2 * kc2][3]);
            unsigned pa2 = packh2(sacc[2 * kc2 + 1][0], sacc[2 * kc2 + 1][1]);
            unsigned pa3 = packh2(sacc[2 * kc2 + 1][2], sacc[2 * kc2 + 1][3]);
#pragma unroll
            for (int g = 0; g < 4; g++) {
                unsigned b0, b1, b2, b3;
                uint32_t addr = vs + (uint32_t)((kc2 * 16 + tvr) * 72
                                                + g * 16 + tvc) * 2u;
                LDSM4T(b0, b1, b2, b3, addr);
                HMMA(oacc[2 * g],     pa0, pa1, pa2, pa3, b0, b1);
                HMMA(oacc[2 * g + 1], pa0, pa1, pa2, pa3, b2, b3);
            }
        }
    }

    const int q0 = m0 + warp * 16 + l4;
    const int q1 = q0 + 8;
    const float inv0 = 1.f / lr0, inv1 = 1.f / lr1;
#pragma unroll
    for (int jd = 0; jd < 8; jd++) {
        int d = hd * DH + jd * 8 + 2 * lm;
        if (q0 < S_) {
            float* p = g_x + ((long)b * S_ + q0) * D_ + d;
            float2 o = *(float2*)p;
            o.x += oacc[jd][0] * inv0;
            o.y += oacc[jd][1] * inv0;
            *(float2*)p = o;
        }
        if (q1 < S_) {
            float* p = g_x + ((long)b * S_ + q1) * D_ + d;
            float2 o = *(float2*)p;
            o.x += oacc[jd][2] * inv1;
            o.y += oacc[jd][3] * inv1;
            *(float2*)p = o;
        }
    }
}

// ---------------- one-shot weight prep (all transposes) ---------------------
__global__ void prep_kernel(
    const float* __restrict__ w1, const float* __restrict__ w2,
    const float* __restrict__ pdW, const float* __restrict__ ppW,
    const float* __restrict__ pcW,
    const float* __restrict__ qW, const float* __restrict__ kW,
    const float* __restrict__ vW)
{
    __shared__ float t[32][33];
    const int bid = blockIdx.x;
    const int tx = threadIdx.x, ty = threadIdx.y;

    if (bid < 10944) {
        const float* src; __half* dst; int K, N, local;
        if (bid < 2304)       { src = w1;                 dst = g_wt + OFF_W1_0; K = 768;  N = 3072; local = bid; }
        else if (bid < 4608)  { src = w1 + (long)D_ * FF; dst = g_wt + OFF_W1_1; K = 768;  N = 3072; local = bid - 2304; }
        else if (bid < 6912)  { src = w2;                 dst = g_wt + OFF_W2_0; K = 3072; N = 768;  local = bid - 4608; }
        else if (bid < 9216)  { src = w2 + (long)FF * D_; dst = g_wt + OFF_W2_1; K = 3072; N = 768;  local = bid - 6912; }
        else if (bid < 9792)  { src = pdW;                dst = g_wt + OFF_PD;   K = 768;  N = 768;  local = bid - 9216; }
        else if (bid < 10368) { src = ppW;                dst = g_wt + OFF_PP;   K = 768;  N = 768;  local = bid - 9792; }
        else                  { src = pcW;                dst = g_wt + OFF_PC;   K = 768;  N = 768;  local = bid - 10368; }
        const int nb = N / 32;
        const int n0 = (local % nb) * 32, k0 = (local / nb) * 32;
#pragma unroll
        for (int i = 0; i < 32; i += 8)
            t[ty + i][tx] = src[(long)(k0 + ty + i) * N + n0 + tx];
        __syncthreads();
#pragma unroll
        for (int i = 0; i < 32; i += 8)
            dst[(long)(n0 + ty + i) * K + k0 + tx] = __float2half_rn(t[tx][ty + i]);
    } else {
        const int local = bid - 10944;           // 0..287
        const int z = local >> 2, tile = local & 3;
        const int l = z / 36, rr = z % 36, m = rr / 12, h = rr % 12;
        const float* src = (m == 0 ? qW : m == 1 ? kW : vW)
                           + ((long)(l * 12 + h) * 64) * 64;
        __half* dst = g_wqkv + (long)z * 4096;
        const int e0 = (tile & 1) * 32, d0 = (tile >> 1) * 32;
#pragma unroll
        for (int i = 0; i < 32; i += 8)
            t[ty + i][tx] = src[(d0 + ty + i) * 64 + e0 + tx];
        __syncthreads();
#pragma unroll
        for (int i = 0; i < 32; i += 8)
            dst[(e0 + ty + i) * 64 + d0 + tx] = __float2half_rn(t[tx][ty + i]);
    }
}

// ---------------- x -> half, plus cls broadcast into g_x (merged) -----------
#define CVTX_BLKS ((B_ * NPATCH * D_ / 2 + 255) / 256)      // 12288
__global__ void cvtx_kernel(const float* __restrict__ x,
                            const float* __restrict__ cls_emb)
{
    const int bid = blockIdx.x;
    if (bid < CVTX_BLKS) {
        long i = ((long)bid * 256 + threadIdx.x) * 2;
        if (i >= (long)B_ * NPATCH * D_) return;
        float2 v = *(const float2*)(x + i);
        *(__half2*)(g_hh + i) = __floats2half2_rn(v.x, v.y);
    } else {
        int idx = (bid - CVTX_BLKS) * 256 + threadIdx.x;
        if (idx >= NCLS * D_) return;
        float v = cls_emb[idx];
        int c = idx / D_, d = idx % D_;
#pragma unroll
        for (int b = 0; b < B_; b++)
            g_x[(long)(b * S_ + NPATCH + c) * D_ + d] = v;
    }
}

// ---------------- LayerNorm, warp-per-row, half output only -----------------
__global__ void __launch_bounds__(256) ln_kernel(
    const float* __restrict__ x, const float* __restrict__ g,
    const float* __restrict__ bta, __half* __restrict__ outh)
{
    const int warp = threadIdx.x >> 5, lane = threadIdx.x & 31;
    const long r = (long)blockIdx.x * 8 + warp;
    const float* xr = x + r * D_;
    float v[24];
    float s = 0.f, s2 = 0.f;
#pragma unroll
    for (int i = 0; i < 6; i++) {
        float4 t = *(const float4*)(xr + i * 128 + lane * 4);
        v[i * 4 + 0] = t.x; v[i * 4 + 1] = t.y;
        v[i * 4 + 2] = t.z; v[i * 4 + 3] = t.w;
        s  += t.x + t.y + t.z + t.w;
        s2 += t.x * t.x + t.y * t.y + t.z * t.z + t.w * t.w;
    }
#pragma unroll
    for (int o = 16; o > 0; o >>= 1) {
        s  += __shfl_xor_sync(0xffffffff, s, o);
        s2 += __shfl_xor_sync(0xffffffff, s2, o);
    }
    float mean = s * (1.f / 768.f);
    float var  = s2 * (1.f / 768.f) - mean * mean;
    float inv  = rsqrtf(var + 1e-5f);
    __half* hrow = outh + r * D_;
#pragma unroll
    for (int i = 0; i < 6; i++) {
        int c = i * 128 + lane * 4;
        float4 gg = *(const float4*)(g + c);
        float4 bb = *(const float4*)(bta + c);
        float o0 = (v[i * 4 + 0] - mean) * inv * gg.x + bb.x;
        float o1 = (v[i * 4 + 1] - mean) * inv * gg.y + bb.y;
        float o2 = (v[i * 4 + 2] - mean) * inv * gg.z + bb.z;
        float o3 = (v[i * 4 + 3] - mean) * inv * gg.w + bb.w;
        uint2 st;
        st.x = packh2(o0, o1);
        st.y = packh2(o2, o3);
        *(uint2*)(hrow + c) = st;
    }
}

// ---------------- merged L2 row normalize: patches then cls -----------------
// grid = 1024 + 19 blocks of 8 warps; bid < 1024 -> g_patches, else g_cls.
__global__ void __launch_bounds__(256) l2norm_kernel()
{
    const int warp = threadIdx.x >> 5, lane = threadIdx.x & 31;
    const int bid = blockIdx.x;
    float* xr;
    if (bid < 1024) xr = g_patches + ((long)bid * 8 + warp) * D_;
    else            xr = g_cls + ((long)(bid - 1024) * 8 + warp) * D_;
    float v[24];
    float s2 = 0.f;
#pragma unroll
    for (int i = 0; i < 6; i++) {
        float4 t = *(const float4*)(xr + i * 128 + lane * 4);
        v[i * 4 + 0] = t.x; v[i * 4 + 1] = t.y;
        v[i * 4 + 2] = t.z; v[i * 4 + 3] = t.w;
        s2 += t.x * t.x + t.y * t.y + t.z * t.z + t.w * t.w;
    }
#pragma unroll
    for (int o = 16; o > 0; o >>= 1)
        s2 += __shfl_xor_sync(0xffffffff, s2, o);
    float inv = rsqrtf(s2);
#pragma unroll
    for (int i = 0; i < 6; i++) {
        float4 t;
        t.x = v[i * 4 + 0] * inv; t.y = v[i * 4 + 1] * inv;
        t.z = v[i * 4 + 2] * inv; t.w = v[i * 4 + 3] * inv;
        *(float4*)(xr + i * 128 + lane * 4) = t;
    }
}

// ---------------- masks + mask-LN fused -------------------------------------
__global__ void __launch_bounds__(256) masks_kernel(
    const float* __restrict__ mg, const float* __restrict__ mb)
{
    __shared__ float pt[64][128];
    __shared__ float cs[NCLS][128];
    __shared__ float sm_m[64][20];
    const int b = blockIdx.y;
    const int t0 = blockIdx.x * 64;
    const int tid = threadIdx.x;
    float acc[5];
#pragma unroll
    for (int i = 0; i < 5; i++) acc[i] = 0.f;

    for (int d0 = 0; d0 < D_; d0 += 128) {
#pragma unroll
        for (int i = 0; i < 8; i++) {
            int f = i * 256 + tid;
            int row = f >> 5, c4 = (f & 31) * 4;
            *(float4*)&pt[row][c4] =
                *(const float4*)(g_patches + (long)(b * NPATCH + t0 + row) * D_ + d0 + c4);
        }
        for (int f = tid; f < NCLS * 32; f += 256) {
            int row = f >> 5, c4 = (f & 31) * 4;
            *(float4*)&cs[row][c4] =
                *(const float4*)(g_cls + (long)(b * NCLS + row) * D_ + d0 + c4);
        }
        __syncthreads();
#pragma unroll
        for (int i = 0; i < 5; i++) {
            int p = i * 256 + tid;
            if (p < 64 * NCLS) {
                int tok = p / NCLS, c = p % NCLS;
                float s = acc[i];
#pragma unroll 8
                for (int d = 0; d < 128; d++)
                    s = fmaf(pt[tok][d], cs[c][d], s);
                acc[i] = s;
            }
        }
        __syncthreads();
    }
#pragma unroll
    for (int i = 0; i < 5; i++) {
        int p = i * 256 + tid;
        if (p < 64 * NCLS) sm_m[p / NCLS][p % NCLS] = acc[i];
    }
    __syncthreads();

    if (tid < 64) {
        const int n = t0 + tid;
        float mean = 0.f;
#pragma unroll
        for (int c = 0; c < NCLS; c++) mean += sm_m[tid][c];
        mean *= (1.f / (float)NCLS);
        float var = 0.f;
#pragma unroll
        for (int c = 0; c < NCLS; c++) {
            float d = sm_m[tid][c] - mean;
            var += d * d;
        }
        var *= (1.f / (float)NCLS);
        float inv = rsqrtf(var + 1e-5f);
        const int gy = n >> 5, gx = n & 31;
#pragma unroll
        for (int c = 0; c < NCLS; c++)
            g_mln[(((long)b * NCLS + c) * GS + gy) * GS + gx] =
                (sm_m[tid][c] - mean) * inv * mg[c] + mb[c];
    }
}

// ---------------- bilinear 32x32 -> 512x512 ---------------------------------
__global__ void __launch_bounds__(256) resize_kernel(float* __restrict__ out)
{
    const int pix = blockIdx.x * 256 + threadIdx.x;
    const int c = blockIdx.y, b = blockIdx.z;
    const int ox = pix & 511, oy = pix >> 9;
    float fx = (ox + 0.5f) * 0.0625f - 0.5f;
    float fy = (oy + 0.5f) * 0.0625f - 0.5f;
    int ix0 = (int)floorf(fx), iy0 = (int)floorf(fy);
    float wx = fx - (float)ix0, wy = fy - (float)iy0;
    int x0 = max(ix0, 0), x1 = min(ix0 + 1, GS - 1);
    int y0 = max(iy0, 0), y1 = min(iy0 + 1, GS - 1);
    const float* m = g_mln + ((long)b * NCLS + c) * GS * GS;
    float v00 = m[y0 * GS + x0], v01 = m[y0 * GS + x1];
    float v10 = m[y1 * GS + x0], v11 = m[y1 * GS + x1];
    float v = (1.f - wy) * ((1.f - wx) * v00 + wx * v01)
            +        wy  * ((1.f - wx) * v10 + wx * v11);
    out[(((long)b * NCLS + c) * IMG + oy) * IMG + ox] = v;
}

// ---------------- host orchestration ----------------------------------------
static void* sym_addr(const void* sym)
{
    void* p = nullptr;
    cudaGetSymbolAddress(&p, sym);
    return p;
}

#define SMEM_H128 ((128 * 40 + 128 * 40) * 2 * 4)   // 81920
#define SMEM_QKV  ((128 * 40 + 64 * 40) * 2 * 4)    // 61440

extern "C" void kernel_launch(void* const* d_in, const int* in_sizes, int n_in,
                              void* d_out, int out_size)
{
    (void)in_sizes; (void)n_in; (void)out_size;
    const float* x    = (const float*)d_in[0];
    const float* pdW  = (const float*)d_in[1];
    const float* pdb  = (const float*)d_in[2];
    const float* cls  = (const float*)d_in[3];
    const float* l1g  = (const float*)d_in[4];
    const float* l1b  = (const float*)d_in[5];
    const float* qW   = (const float*)d_in[6];
    const float* qb   = (const float*)d_in[7];
    const float* kW   = (const float*)d_in[8];
    const float* kb   = (const float*)d_in[9];
    const float* vW   = (const float*)d_in[10];
    const float* vb   = (const float*)d_in[11];
    const float* l2g  = (const float*)d_in[12];
    const float* l2b  = (const float*)d_in[13];
    const float* w1   = (const float*)d_in[14];
    const float* b1   = (const float*)d_in[15];
    const float* w2   = (const float*)d_in[16];
    const float* b2   = (const float*)d_in[17];
    const float* ppW  = (const float*)d_in[18];
    const float* pcW  = (const float*)d_in[19];
    const float* dg   = (const float*)d_in[20];
    const float* db   = (const float*)d_in[21];
    const float* mg   = (const float*)d_in[22];
    const float* mb   = (const float*)d_in[23];
    float* out = (float*)d_out;

    float*  gx   = (float*)sym_addr(g_x);
    __half* ghh  = (__half*)sym_addr(g_hh);
    __half* gff  = (__half*)sym_addr(g_ff);
    float*  gpt  = (float*)sym_addr(g_patches);
    float*  gcl  = (float*)sym_addr(g_cls);
    __half* wt   = (__half*)sym_addr(g_wt);
    __half* wqkv = (__half*)sym_addr(g_wqkv);

    cudaFuncSetAttribute(hgemm<128>,
                         cudaFuncAttributeMaxDynamicSharedMemorySize, SMEM_H128);
    cudaFuncSetAttribute(qkv_gemm,
                         cudaFuncAttributeMaxDynamicSharedMemorySize, SMEM_QKV);
    cudaFuncSetAttribute(fattn_kernel,
                         cudaFuncAttributeMaxDynamicSharedMemorySize, FA_SMEM);

    const dim3 blk(256);
    const dim3 tsb(32, 8);
    const int mtiles = (M_ + 127) / 128;      // 66

    // ---- one-shot prep: weight transposes; x->half + cls broadcast ----
    prep_kernel<<<11232, tsb>>>(w1, w2, pdW, ppW, pcW, qW, kW, vW);
    cvtx_kernel<<<CVTX_BLKS + (NCLS * D_ + 255) / 256, 256>>>(x, cls);

    // ---- x(half) @ proj_dec + b -> g_x patch rows ----
    hgemm<128><<<dim3(6, 8, B_), blk, SMEM_H128>>>(
        ghh, wt + OFF_PD, pdb, gx,
        NPATCH, D_, D_, D_, D_, D_,
        1, (long)NPATCH * D_, 0, 0, 0, (long)S_ * D_, 0, 1);

    for (int l = 0; l < 2; l++) {
        ln_kernel<<<M_ / 8, blk>>>(gx, l1g + l * D_, l1b + l * D_, ghh);

        qkv_gemm<<<dim3(1, mtiles, 36), blk, SMEM_QKV>>>(
            ghh, wqkv + (long)l * 36 * 4096,
            qb + (long)l * NH * DH, kb + (long)l * NH * DH, vb + (long)l * NH * DH);

        fattn_kernel<<<dim3((S_ + 127) / 128, BHD), blk, FA_SMEM>>>();

        ln_kernel<<<M_ / 8, blk>>>(gx, l2g + l * D_, l2b + l * D_, ghh);

        hgemm<128><<<dim3(FF / 128, mtiles, 1), blk, SMEM_H128>>>(
            ghh, wt + (l ? OFF_W1_1 : OFF_W1_0), b1 + (long)l * FF, gff,
            M_, FF, D_, D_, D_, FF,
            1, 0, 0, 0, 0, 0, 0, 1 | 2 | 16);
        hgemm<128><<<dim3(D_ / 128, mtiles, 1), blk, SMEM_H128>>>(
            gff, wt + (l ? OFF_W2_1 : OFF_W2_0), b2 + (long)l * D_, gx,
            M_, D_, FF, FF, FF, D_,
            1, 0, 0, 0, 0, 0, 0, 1 | 4);
    }

    ln_kernel<<<M_ / 8, blk>>>(gx, dg, db, ghh);

    hgemm<128><<<dim3(6, 8, B_), blk, SMEM_H128>>>(
        ghh, wt + OFF_PP, nullptr, gpt,
        NPATCH, D_, D_, D_, D_, D_,
        1, (long)S_ * D_, 0, 0, 0, (long)NPATCH * D_, 0, 0);
    hgemm<128><<<dim3(6, 1, B_), blk, SMEM_H128>>>(
        ghh + (long)NPATCH * D_, wt + OFF_PC, nullptr, gcl,
        NCLS, D_, D_, D_, D_, D_,
        1, (long)S_ * D_, 0, 0, 0, (long)NCLS * D_, 0, 0);

    l2norm_kernel<<<1024 + NCLS, blk>>>();

    masks_kernel<<<dim3(NPATCH / 64, B_), blk>>>(mg, mb);
    resize_kernel<<<dim3(IMG * IMG / 256, NCLS, B_), blk>>>(out);
}

// round 17
// speedup vs baseline: 1.3932x; 1.1107x over previous
// R17: hgemm KC 32->64 (3-stage, stride-72 smem as proven in fattn) to halve
// barrier rounds in the MLP GEMMs; everything else identical to R16.
#include <cuda_runtime.h>
#include <cuda_fp16.h>
#include <math.h>
#include <stdint.h>

// ---------------- problem constants ----------------
#define B_      8
#define S_      1043
#define NPATCH  1024
#define NCLS    19
#define D_      768
#define NH      12
#define DH      64
#define FF      3072
#define GS      32
#define IMG     512
#define M_      (B_*S_)         // 8344
#define BHD     (B_*NH)         // 96
#define MPAD    8576
#define TKV     64
#define NKT     17              // ceil(S_/64)

// ---------------- scratch ----------------------------------------------------
__device__ float g_x[(size_t)M_ * D_];
__device__ __align__(128) __half g_hh[(size_t)MPAD * D_];
#define MDSEG ((size_t)M_ * D_ + 128 * D_)
__device__ __align__(128) __half g_qkvh[3 * MDSEG];   // q | k | v segments
__device__ __align__(128) __half g_ff[(size_t)MPAD * FF];
__device__ float g_patches[(size_t)B_ * NPATCH * D_];
__device__ float g_cls[(size_t)B_ * NCLS * D_ + 40 * D_];  // slack for merged l2norm tail
__device__ float g_mln[(size_t)B_ * NCLS * GS * GS];

#define WTOT 11206656
__device__ __align__(128) __half g_wt[WTOT];
#define OFF_W1_0 0
#define OFF_W1_1 2359296
#define OFF_W2_0 4718592
#define OFF_W2_1 7077888
#define OFF_PD   9437184
#define OFF_PP   10027008
#define OFF_PC   10616832
// per-head transposed qkv weights: [(l*3+m)*12+h] x [e][d] 64x64
__device__ __align__(128) __half g_wqkv[72 * 4096];

// ---------------- helpers ----------------------------------------------------
__device__ __forceinline__ float gelu_exact(float v) {
    return 0.5f * v * (1.f + erff(v * 0.70710678118654752f));
}
__device__ __forceinline__ uint32_t smem_to_u32(const void* p) {
    uint32_t a;
    asm("{ .reg .u64 t; cvta.to.shared.u64 t, %1; cvt.u32.u64 %0, t; }"
        : "=r"(a) : "l"(p));
    return a;
}
__device__ __forceinline__ unsigned packh2(float a, float b) {
    __half2 h = __floats2half2_rn(a, b);
    return *(unsigned*)&h;
}
#define CP16(dst, src) \
    asm volatile("cp.async.cg.shared.global [%0], [%1], 16;" :: "r"(dst), "l"(src))
#define CPCOMMIT() asm volatile("cp.async.commit_group;")
#define CPWAIT0()  asm volatile("cp.async.wait_group 0;")
#define CPWAIT1()  asm volatile("cp.async.wait_group 1;")
#define CPWAIT2()  asm volatile("cp.async.wait_group 2;")

#define HMMA(acc, a0, a1, a2, a3, b0, b1) \
    asm volatile( \
        "mma.sync.aligned.m16n8k16.row.col.f32.f16.f16.f32 " \
        "{%0,%1,%2,%3},{%4,%5,%6,%7},{%8,%9},{%0,%1,%2,%3};" \
        : "+f"((acc)[0]), "+f"((acc)[1]), "+f"((acc)[2]), "+f"((acc)[3]) \
        : "r"(a0), "r"(a1), "r"(a2), "r"(a3), "r"(b0), "r"(b1))

#define LDSM4(r0, r1, r2, r3, addr) \
    asm volatile("ldmatrix.sync.aligned.m8n8.x4.shared.b16 {%0,%1,%2,%3}, [%4];" \
        : "=r"(r0), "=r"(r1), "=r"(r2), "=r"(r3) : "r"(addr))
#define LDSM4T(r0, r1, r2, r3, addr) \
    asm volatile("ldmatrix.sync.aligned.m8n8.x4.trans.shared.b16 {%0,%1,%2,%3}, [%4];" \
        : "=r"(r0), "=r"(r1), "=r"(r2), "=r"(r3) : "r"(addr))

// ---------------- fp16 tensor-core GEMM (128x128 tile, KC=64, 3-stage) -------
// C[M,*] = A[M,K] @ B[N,K]^T. flags: 1 bias, 2 gelu, 4 +=C(fp32), 16 C half.
// smem row stride 72 halfs (matches fattn's proven conflict-free layout).
#define H_ASTH (128 * 72)
#define H_BSTH (128 * 72)
#define H_STH  (H_ASTH + H_BSTH)
#define SMEM_H128 (3 * H_STH * 2)          // 110592 B -> 2 blocks/SM
__global__ void __launch_bounds__(256) hgemm(
    const __half* __restrict__ A, const __half* __restrict__ Bm,
    const float* __restrict__ bias, void* __restrict__ Cv,
    int M, int Nlim, int K, int lda, int ldb, int ldc,
    int HZ, long sA, long hA, long sB, long hB, long sC, long hC,
    int flags)
{
    extern __shared__ __half smh[];

    const int z = blockIdx.z;
    A  += (long)(z / HZ) * sA + (long)(z % HZ) * hA;
    Bm += (long)(z / HZ) * sB + (long)(z % HZ) * hB;

    const int tid = threadIdx.x, warp = tid >> 5, lane = tid & 31;
    const int wm = warp & 3, wn = warp >> 2;
    const int l4 = lane >> 2, lm = lane & 3;
    const int m0 = blockIdx.y * 128, n0 = blockIdx.x * 128;
    const uint32_t sb = smem_to_u32(smh);
    const int nch = K >> 6;

    const int arow = (lane & 15), acol8 = (lane >> 4) * 8;
    const int bn_l = ((lane >> 4) & 1) * 8 + (lane & 7);
    const int bc_l = ((lane >> 3) & 1) * 8;

    auto issue = [&](int kc) {
        if (kc < nch) {
            const int st = kc % 3;
            const uint32_t ab = sb + (uint32_t)(st * H_STH) * 2u;
            const uint32_t bb = ab + (uint32_t)H_ASTH * 2u;
            const int k0 = kc << 6;
            const __half* Ap = A + (long)m0 * lda + k0;
#pragma unroll
            for (int i = 0; i < 4; i++) {
                int q = i * 256 + tid;
                int row = q >> 3, seg = (q & 7) * 8;
                CP16(ab + (uint32_t)(row * 72 + seg) * 2u,
                     Ap + (long)row * lda + seg);
            }
            const __half* Bp = Bm + (long)n0 * ldb + k0;
#pragma unroll
            for (int i = 0; i < 4; i++) {
                int q = i * 256 + tid;
                int row = q >> 3, seg = (q & 7) * 8;
                CP16(bb + (uint32_t)(row * 72 + seg) * 2u,
                     Bp + (long)row * ldb + seg);
            }
        }
        CPCOMMIT();
    };

    float acc[2][8][4];
#pragma unroll
    for (int i = 0; i < 2; i++)
#pragma unroll
        for (int j = 0; j < 8; j++)
#pragma unroll
            for (int c = 0; c < 4; c++) acc[i][j][c] = 0.f;

    issue(0); issue(1);

    for (int c = 0; c < nch; c++) {
        CPWAIT1();
        __syncthreads();
        issue(c + 2);

        const uint32_t as = sb + (uint32_t)((c % 3) * H_STH) * 2u;
        const uint32_t bs = as + (uint32_t)H_ASTH * 2u;
#pragma unroll
        for (int kk = 0; kk < 64; kk += 16) {
            unsigned af[2][4];
#pragma unroll
            for (int i = 0; i < 2; i++) {
                uint32_t addr = as + (uint32_t)((wm * 32 + i * 16 + arow) * 72
                                                + kk + acol8) * 2u;
                LDSM4(af[i][0], af[i][1], af[i][2], af[i][3], addr);
            }
#pragma unroll
            for (int g = 0; g < 4; g++) {
                unsigned b0, b1, b2, b3;
                uint32_t addr = bs + (uint32_t)((wn * 64 + g * 16 + bn_l) * 72
                                                + kk + bc_l) * 2u;
                LDSM4(b0, b1, b2, b3, addr);
#pragma unroll
                for (int i = 0; i < 2; i++) {
                    HMMA(acc[i][2 * g],     af[i][0], af[i][1], af[i][2], af[i][3], b0, b1);
                    HMMA(acc[i][2 * g + 1], af[i][0], af[i][1], af[i][2], af[i][3], b2, b3);
                }
            }
        }
    }

    float*  Cf = (float*)Cv  + (long)(z / HZ) * sC + (long)(z % HZ) * hC;
    __half* Ch = (__half*)Cv + (long)(z / HZ) * sC + (long)(z % HZ) * hC;
#pragma unroll
    for (int i = 0; i < 2; i++)
#pragma unroll
        for (int j = 0; j < 8; j++)
#pragma unroll
            for (int h = 0; h < 2; h++) {
                int row = m0 + wm * 32 + i * 16 + l4 + h * 8;
                if (row >= M) continue;
                int col = n0 + wn * 64 + j * 8 + lm * 2;
                if (col >= Nlim) continue;
                float v0 = acc[i][j][h * 2 + 0];
                float v1 = acc[i][j][h * 2 + 1];
                bool has1 = (col + 1 < Nlim);
                if (flags & 1) {
                    v0 += bias[col];
                    if (has1) v1 += bias[col + 1];
                }
                if (flags & 2)  { v0 = gelu_exact(v0); v1 = gelu_exact(v1); }
                if (flags & 16) {
                    __half* hp = Ch + (long)row * ldc + col;
                    if (has1) *(__half2*)hp = __floats2half2_rn(v0, v1);
                    else      hp[0] = __float2half_rn(v0);
                } else {
                    float* cp = Cf + (long)row * ldc + col;
                    if (has1) {
                        if (flags & 4) { float2 o = *(float2*)cp; v0 += o.x; v1 += o.y; }
                        float2 st; st.x = v0; st.y = v1;
                        *(float2*)cp = st;
                    } else {
                        if (flags & 4) v0 += cp[0];
                        cp[0] = v0;
                    }
                }
            }
}

// ---------------- fused qkv GEMM (R11-proven): z = m*12+h --------------------
#define QKV_ASTH (128 * 40)
#define QKV_BSTH (64 * 40)
#define QKV_STH  (QKV_ASTH + QKV_BSTH)
__global__ void __launch_bounds__(256) qkv_gemm(
    const __half* __restrict__ A, const __half* __restrict__ Wl,
    const float* __restrict__ qb, const float* __restrict__ kb,
    const float* __restrict__ vb)
{
    extern __shared__ __half smh[];
    const int z = blockIdx.z;
    const int m = z / NH, h = z % NH;
    const __half* Bm = Wl + (long)z * 4096;      // [64 e][64 d]
    const float* bias = (m == 0 ? qb : m == 1 ? kb : vb) + h * DH;
    const float scale = (m == 0) ? 0.125f : 1.f;
    __half* C = g_qkvh + (size_t)m * MDSEG + h * DH;

    const int tid = threadIdx.x, warp = tid >> 5, lane = tid & 31;
    const int wm = warp & 3, wn = warp >> 2;
    const int l4 = lane >> 2, lm = lane & 3;
    const int m0 = blockIdx.y * 128;
    const uint32_t sb = smem_to_u32(smh);

    const int arow = (lane & 15), acol8 = (lane >> 4) * 8;
    const int bn_l = ((lane >> 4) & 1) * 8 + (lane & 7);
    const int bc_l = ((lane >> 3) & 1) * 8;

    auto issue = [&](int kc) {
        if (kc < 2) {
            const int st = kc & 3;
            const uint32_t ab = sb + (uint32_t)(st * QKV_STH) * 2u;
            const uint32_t bb = ab + (uint32_t)QKV_ASTH * 2u;
            const int k0 = kc << 5;
            const __half* Ap = A + (long)m0 * D_ + h * DH + k0;   // head slice
#pragma unroll
            for (int i = 0; i < 2; i++) {
                int q = i * 256 + tid;
                int row = q >> 2, seg = (q & 3) * 8;
                CP16(ab + (uint32_t)(row * 40 + seg) * 2u,
                     Ap + (long)row * D_ + seg);
            }
            {
                int row = tid >> 2, seg = (tid & 3) * 8;
                CP16(bb + (uint32_t)(row * 40 + seg) * 2u,
                     Bm + (long)row * DH + k0 + seg);
            }
        }
        CPCOMMIT();
    };

    float acc[2][4][4];
#pragma unroll
    for (int i = 0; i < 2; i++)
#pragma unroll
        for (int j = 0; j < 4; j++)
#pragma unroll
            for (int c = 0; c < 4; c++) acc[i][j][c] = 0.f;

    issue(0); issue(1); issue(2);

    for (int c = 0; c < 2; c++) {
        CPWAIT2();
        __syncthreads();
        issue(c + 3);
        const uint32_t as = sb + (uint32_t)((c & 3) * QKV_STH) * 2u;
        const uint32_t bs = as + (uint32_t)QKV_ASTH * 2u;
#pragma unroll
        for (int kk = 0; kk < 32; kk += 16) {
            unsigned af[2][4];
#pragma unroll
            for (int i = 0; i < 2; i++) {
                uint32_t addr = as + (uint32_t)((wm * 32 + i * 16 + arow) * 40
                                                + kk + acol8) * 2u;
                LDSM4(af[i][0], af[i][1], af[i][2], af[i][3], addr);
            }
#pragma unroll
            for (int g = 0; g < 2; g++) {
                unsigned b0, b1, b2, b3;
                uint32_t addr = bs + (uint32_t)((wn * 32 + g * 16 + bn_l) * 40
                                                + kk + bc_l) * 2u;
                LDSM4(b0, b1, b2, b3, addr);
#pragma unroll
                for (int i = 0; i < 2; i++) {
                    HMMA(acc[i][2 * g],     af[i][0], af[i][1], af[i][2], af[i][3], b0, b1);
                    HMMA(acc[i][2 * g + 1], af[i][0], af[i][1], af[i][2], af[i][3], b2, b3);
                }
            }
        }
    }

#pragma unroll
    for (int i = 0; i < 2; i++)
#pragma unroll
        for (int j = 0; j < 4; j++)
#pragma unroll
            for (int hh = 0; hh < 2; hh++) {
                int row = m0 + wm * 32 + i * 16 + l4 + hh * 8;
                if (row >= M_) continue;
                int col = wn * 32 + j * 8 + lm * 2;
                float v0 = (acc[i][j][hh * 2 + 0] + bias[col])     * scale;
                float v1 = (acc[i][j][hh * 2 + 1] + bias[col + 1]) * scale;
                *(__half2*)(C + (long)row * D_ + col) = __floats2half2_rn(v0, v1);
            }
}

// ---------------- fused flash attention (V via trans-ldmatrix) --------------
#define FA_QS 0
#define FA_KS (128 * 72)
#define FA_VS (128 * 72 + 2 * 64 * 72)
#define FA_SMEM ((128 * 72 + 4 * 64 * 72) * 2)
__global__ void __launch_bounds__(256) fattn_kernel()
{
    extern __shared__ __half sh[];
    const int z = blockIdx.y;
    const int b = z / NH, hd = z % NH;
    const int m0 = blockIdx.x * 128;
    const int tid = threadIdx.x, warp = tid >> 5, lane = tid & 31;
    const int l4 = lane >> 2, lm = lane & 3;
    const uint32_t sb = smem_to_u32(sh);

    const __half* Qg = g_qkvh + 0 * MDSEG + ((long)b * S_ + m0) * D_ + hd * DH;
    const __half* Kg = g_qkvh + 1 * MDSEG + (long)b * S_ * D_ + hd * DH;
    const __half* Vg = g_qkvh + 2 * MDSEG + (long)b * S_ * D_ + hd * DH;

    const int arow = (lane & 15), acol8 = (lane >> 4) * 8;
    const int bn_l = ((lane >> 4) & 1) * 8 + (lane & 7);
    const int bc_l = ((lane >> 3) & 1) * 8;
    const int tvr = ((lane >> 3) & 1) * 8 + (lane & 7);
    const int tvc = ((lane >> 4) & 1) * 8;

    auto loadKV = [&](int kt) {
        const int st = kt & 1;
        const __half* Kp = Kg + (long)(kt * TKV) * D_;
        const __half* Vp = Vg + (long)(kt * TKV) * D_;
        const uint32_t kb = sb + (uint32_t)(FA_KS + st * 64 * 72) * 2u;
        const uint32_t vb = sb + (uint32_t)(FA_VS + st * 64 * 72) * 2u;
#pragma unroll
        for (int i = 0; i < 2; i++) {
            int q = i * 256 + tid;
            int row = q >> 3, seg = (q & 7) * 8;
            CP16(kb + (uint32_t)(row * 72 + seg) * 2u, Kp + (long)row * D_ + seg);
        }
#pragma unroll
        for (int i = 0; i < 2; i++) {
            int q = i * 256 + tid;
            int row = q >> 3, seg = (q & 7) * 8;
            CP16(vb + (uint32_t)(row * 72 + seg) * 2u, Vp + (long)row * D_ + seg);
        }
    };

#pragma unroll
    for (int i = 0; i < 4; i++) {
        int q = i * 256 + tid;
        int row = q >> 3, seg = (q & 7) * 8;
        CP16(sb + (uint32_t)(FA_QS + row * 72 + seg) * 2u, Qg + (long)row * D_ + seg);
    }
    loadKV(0);
    CPCOMMIT();
    CPWAIT0();
    __syncthreads();

    unsigned qa[4][4];
#pragma unroll
    for (int kc = 0; kc < 4; kc++) {
        uint32_t addr = sb + (uint32_t)(FA_QS + (warp * 16 + arow) * 72
                                        + kc * 16 + acol8) * 2u;
        LDSM4(qa[kc][0], qa[kc][1], qa[kc][2], qa[kc][3], addr);
    }

    float oacc[8][4];
#pragma unroll
    for (int j = 0; j < 8; j++)
#pragma unroll
        for (int c = 0; c < 4; c++) oacc[j][c] = 0.f;
    float mr0 = -1e30f, mr1 = -1e30f, lr0 = 0.f, lr1 = 0.f;

    for (int kt = 0; kt < NKT; kt++) {
        __syncthreads();
        if (kt + 1 < NKT) { loadKV(kt + 1); CPCOMMIT(); CPWAIT1(); }
        else              { CPWAIT0(); }
        __syncthreads();

        const uint32_t ks = sb + (uint32_t)(FA_KS + (kt & 1) * 64 * 72) * 2u;
        const uint32_t vs = sb + (uint32_t)(FA_VS + (kt & 1) * 64 * 72) * 2u;

        float sacc[8][4];
#pragma unroll
        for (int j = 0; j < 8; j++)
#pragma unroll
            for (int c = 0; c < 4; c++) sacc[j][c] = 0.f;
#pragma unroll
        for (int kc = 0; kc < 4; kc++)
#pragma unroll
            for (int g = 0; g < 4; g++) {
                unsigned b0, b1, b2, b3;
                uint32_t addr = ks + (uint32_t)((g * 16 + bn_l) * 72
                                                + kc * 16 + bc_l) * 2u;
                LDSM4(b0, b1, b2, b3, addr);
                HMMA(sacc[2 * g],     qa[kc][0], qa[kc][1], qa[kc][2], qa[kc][3], b0, b1);
                HMMA(sacc[2 * g + 1], qa[kc][0], qa[kc][1], qa[kc][2], qa[kc][3], b2, b3);
            }

        const int base = kt * TKV;
        if (base + TKV > S_) {
#pragma unroll
            for (int j = 0; j < 8; j++) {
                int c0 = base + j * 8 + 2 * lm;
                if (c0 >= S_)     { sacc[j][0] = -1e30f; sacc[j][2] = -1e30f; }
                if (c0 + 1 >= S_) { sacc[j][1] = -1e30f; sacc[j][3] = -1e30f; }
            }
        }

        float tm0 = -1e30f, tm1 = -1e30f;
#pragma unroll
        for (int j = 0; j < 8; j++) {
            tm0 = fmaxf(tm0, fmaxf(sacc[j][0], sacc[j][1]));
            tm1 = fmaxf(tm1, fmaxf(sacc[j][2], sacc[j][3]));
        }
        tm0 = fmaxf(tm0, __shfl_xor_sync(0xffffffff, tm0, 1));
        tm0 = fmaxf(tm0, __shfl_xor_sync(0xffffffff, tm0, 2));
        tm1 = fmaxf(tm1, __shfl_xor_sync(0xffffffff, tm1, 1));
        tm1 = fmaxf(tm1, __shfl_xor_sync(0xffffffff, tm1, 2));
        float mn0 = fmaxf(mr0, tm0), mn1 = fmaxf(mr1, tm1);
        float sc0 = __expf(mr0 - mn0), sc1 = __expf(mr1 - mn1);
        float rs0 = 0.f, rs1 = 0.f;
#pragma unroll
        for (int j = 0; j < 8; j++) {
            sacc[j][0] = __expf(sacc[j][0] - mn0);
            sacc[j][1] = __expf(sacc[j][1] - mn0);
            sacc[j][2] = __expf(sacc[j][2] - mn1);
            sacc[j][3] = __expf(sacc[j][3] - mn1);
            rs0 += sacc[j][0] + sacc[j][1];
            rs1 += sacc[j][2] + sacc[j][3];
        }
        rs0 += __shfl_xor_sync(0xffffffff, rs0, 1);
        rs0 += __shfl_xor_sync(0xffffffff, rs0, 2);
        rs1 += __shfl_xor_sync(0xffffffff, rs1, 1);
        rs1 += __shfl_xor_sync(0xffffffff, rs1, 2);
        lr0 = lr0 * sc0 + rs0;
        lr1 = lr1 * sc1 + rs1;
        mr0 = mn0; mr1 = mn1;
#pragma unroll
        for (int j = 0; j < 8; j++) {
            oacc[j][0] *= sc0; oacc[j][1] *= sc0;
            oacc[j][2] *= sc1; oacc[j][3] *= sc1;
        }

#pragma unroll
        for (int kc2 = 0; kc2 < 4; kc2++) {
            unsigned pa0 = packh2(sacc[2 * kc2][0],     sacc[2 * kc2][1]);
            unsigned pa1 = packh2(sacc[2 * kc2][2],     sacc[2 * kc2][3]);
            unsigned pa2 = packh2(sacc[2 * kc2 + 1][0], sacc[2 * kc2 + 1][1]);
            unsigned pa3 = packh2(sacc[2 * kc2 + 1][2], sacc[2 * kc2 + 1][3]);
#pragma unroll
            for (int g = 0; g < 4; g++) {
                unsigned b0, b1, b2, b3;
                uint32_t addr = vs + (uint32_t)((kc2 * 16 + tvr) * 72
                                                + g * 16 + tvc) * 2u;
                LDSM4T(b0, b1, b2, b3, addr);
                HMMA(oacc[2 * g],     pa0, pa1, pa2, pa3, b0, b1);
                HMMA(oacc[2 * g + 1], pa0, pa1, pa2, pa3, b2, b3);
            }
        }
    }

    const int q0 = m0 + warp * 16 + l4;
    const int q1 = q0 + 8;
    const float inv0 = 1.f / lr0, inv1 = 1.f / lr1;
#pragma unroll
    for (int jd = 0; jd < 8; jd++) {
        int d = hd * DH + jd * 8 + 2 * lm;
        if (q0 < S_) {
            float* p = g_x + ((long)b * S_ + q0) * D_ + d;
            float2 o = *(float2*)p;
            o.x += oacc[jd][0] * inv0;
            o.y += oacc[jd][1] * inv0;
            *(float2*)p = o;
        }
        if (q1 < S_) {
            float* p = g_x + ((long)b * S_ + q1) * D_ + d;
            float2 o = *(float2*)p;
            o.x += oacc[jd][2] * inv1;
            o.y += oacc[jd][3] * inv1;
            *(float2*)p = o;
        }
    }
}

// ---------------- one-shot weight prep (all transposes) ---------------------
__global__ void prep_kernel(
    const float* __restrict__ w1, const float* __restrict__ w2,
    const float* __restrict__ pdW, const float* __restrict__ ppW,
    const float* __restrict__ pcW,
    const float* __restrict__ qW, const float* __restrict__ kW,
    const float* __restrict__ vW)
{
    __shared__ float t[32][33];
    const int bid = blockIdx.x;
    const int tx = threadIdx.x, ty = threadIdx.y;

    if (bid < 10944) {
        const float* src; __half* dst; int K, N, local;
        if (bid < 2304)       { src = w1;                 dst = g_wt + OFF_W1_0; K = 768;  N = 3072; local = bid; }
        else if (bid < 4608)  { src = w1 + (long)D_ * FF; dst = g_wt + OFF_W1_1; K = 768;  N = 3072; local = bid - 2304; }
        else if (bid < 6912)  { src = w2;                 dst = g_wt + OFF_W2_0; K = 3072; N = 768;  local = bid - 4608; }
        else if (bid < 9216)  { src = w2 + (long)FF * D_; dst = g_wt + OFF_W2_1; K = 3072; N = 768;  local = bid - 6912; }
        else if (bid < 9792)  { src = pdW;                dst = g_wt + OFF_PD;   K = 768;  N = 768;  local = bid - 9216; }
        else if (bid < 10368) { src = ppW;                dst = g_wt + OFF_PP;   K = 768;  N = 768;  local = bid - 9792; }
        else                  { src = pcW;                dst = g_wt + OFF_PC;   K = 768;  N = 768;  local = bid - 10368; }
        const int nb = N / 32;
        const int n0 = (local % nb) * 32, k0 = (local / nb) * 32;
#pragma unroll
        for (int i = 0; i < 32; i += 8)
            t[ty + i][tx] = src[(long)(k0 + ty + i) * N + n0 + tx];
        __syncthreads();
#pragma unroll
        for (int i = 0; i < 32; i += 8)
            dst[(long)(n0 + ty + i) * K + k0 + tx] = __float2half_rn(t[tx][ty + i]);
    } else {
        const int local = bid - 10944;           // 0..287
        const int z = local >> 2, tile = local & 3;
        const int l = z / 36, rr = z % 36, m = rr / 12, h = rr % 12;
        const float* src = (m == 0 ? qW : m == 1 ? kW : vW)
                           + ((long)(l * 12 + h) * 64) * 64;
        __half* dst = g_wqkv + (long)z * 4096;
        const int e0 = (tile & 1) * 32, d0 = (tile >> 1) * 32;
#pragma unroll
        for (int i = 0; i < 32; i += 8)
            t[ty + i][tx] = src[(d0 + ty + i) * 64 + e0 + tx];
        __syncthreads();
#pragma unroll
        for (int i = 0; i < 32; i += 8)
            dst[(e0 + ty + i) * 64 + d0 + tx] = __float2half_rn(t[tx][ty + i]);
    }
}

// ---------------- x -> half, plus cls broadcast into g_x (merged) -----------
#define CVTX_BLKS ((B_ * NPATCH * D_ / 2 + 255) / 256)      // 12288
__global__ void cvtx_kernel(const float* __restrict__ x,
                            const float* __restrict__ cls_emb)
{
    const int bid = blockIdx.x;
    if (bid < CVTX_BLKS) {
        long i = ((long)bid * 256 + threadIdx.x) * 2;
        if (i >= (long)B_ * NPATCH * D_) return;
        float2 v = *(const float2*)(x + i);
        *(__half2*)(g_hh + i) = __floats2half2_rn(v.x, v.y);
    } else {
        int idx = (bid - CVTX_BLKS) * 256 + threadIdx.x;
        if (idx >= NCLS * D_) return;
        float v = cls_emb[idx];
        int c = idx / D_, d = idx % D_;
#pragma unroll
        for (int b = 0; b < B_; b++)
            g_x[(long)(b * S_ + NPATCH + c) * D_ + d] = v;
    }
}

// ---------------- LayerNorm, warp-per-row, half output only -----------------
__global__ void __launch_bounds__(256) ln_kernel(
    const float* __restrict__ x, const float* __restrict__ g,
    const float* __restrict__ bta, __half* __restrict__ outh)
{
    const int warp = threadIdx.x >> 5, lane = threadIdx.x & 31;
    const long r = (long)blockIdx.x * 8 + warp;
    const float* xr = x + r * D_;
    float v[24];
    float s = 0.f, s2 = 0.f;
#pragma unroll
    for (int i = 0; i < 6; i++) {
        float4 t = *(const float4*)(xr + i * 128 + lane * 4);
        v[i * 4 + 0] = t.x; v[i * 4 + 1] = t.y;
        v[i * 4 + 2] = t.z; v[i * 4 + 3] = t.w;
        s  += t.x + t.y + t.z + t.w;
        s2 += t.x * t.x + t.y * t.y + t.z * t.z + t.w * t.w;
    }
#pragma unroll
    for (int o = 16; o > 0; o >>= 1) {
        s  += __shfl_xor_sync(0xffffffff, s, o);
        s2 += __shfl_xor_sync(0xffffffff, s2, o);
    }
    float mean = s * (1.f / 768.f);
    float var  = s2 * (1.f / 768.f) - mean * mean;
    float inv  = rsqrtf(var + 1e-5f);
    __half* hrow = outh + r * D_;
#pragma unroll
    for (int i = 0; i < 6; i++) {
        int c = i * 128 + lane * 4;
        float4 gg = *(const float4*)(g + c);
        float4 bb = *(const float4*)(bta + c);
        float o0 = (v[i * 4 + 0] - mean) * inv * gg.x + bb.x;
        float o1 = (v[i * 4 + 1] - mean) * inv * gg.y + bb.y;
        float o2 = (v[i * 4 + 2] - mean) * inv * gg.z + bb.z;
        float o3 = (v[i * 4 + 3] - mean) * inv * gg.w + bb.w;
        uint2 st;
        st.x = packh2(o0, o1);
        st.y = packh2(o2, o3);
        *(uint2*)(hrow + c) = st;
    }
}

// ---------------- merged L2 row normalize: patches then cls -----------------
__global__ void __launch_bounds__(256) l2norm_kernel()
{
    const int warp = threadIdx.x >> 5, lane = threadIdx.x & 31;
    const int bid = blockIdx.x;
    float* xr;
    if (bid < 1024) xr = g_patches + ((long)bid * 8 + warp) * D_;
    else            xr = g_cls + ((long)(bid - 1024) * 8 + warp) * D_;
    float v[24];
    float s2 = 0.f;
#pragma unroll
    for (int i = 0; i < 6; i++) {
        float4 t = *(const float4*)(xr + i * 128 + lane * 4);
        v[i * 4 + 0] = t.x; v[i * 4 + 1] = t.y;
        v[i * 4 + 2] = t.z; v[i * 4 + 3] = t.w;
        s2 += t.x * t.x + t.y * t.y + t.z * t.z + t.w * t.w;
    }
#pragma unroll
    for (int o = 16; o > 0; o >>= 1)
        s2 += __shfl_xor_sync(0xffffffff, s2, o);
    float inv = rsqrtf(s2);
#pragma unroll
    for (int i = 0; i < 6; i++) {
        float4 t;
        t.x = v[i * 4 + 0] * inv; t.y = v[i * 4 + 1] * inv;
        t.z = v[i * 4 + 2] * inv; t.w = v[i * 4 + 3] * inv;
        *(float4*)(xr + i * 128 + lane * 4) = t;
    }
}

// ---------------- masks + mask-LN fused -------------------------------------
__global__ void __launch_bounds__(256) masks_kernel(
    const float* __restrict__ mg, const float* __restrict__ mb)
{
    __shared__ float pt[64][128];
    __shared__ float cs[NCLS][128];
    __shared__ float sm_m[64][20];
    const int b = blockIdx.y;
    const int t0 = blockIdx.x * 64;
    const int tid = threadIdx.x;
    float acc[5];
#pragma unroll
    for (int i = 0; i < 5; i++) acc[i] = 0.f;

    for (int d0 = 0; d0 < D_; d0 += 128) {
#pragma unroll
        for (int i = 0; i < 8; i++) {
            int f = i * 256 + tid;
            int row = f >> 5, c4 = (f & 31) * 4;
            *(float4*)&pt[row][c4] =
                *(const float4*)(g_patches + (long)(b * NPATCH + t0 + row) * D_ + d0 + c4);
        }
        for (int f = tid; f < NCLS * 32; f += 256) {
            int row = f >> 5, c4 = (f & 31) * 4;
            *(float4*)&cs[row][c4] =
                *(const float4*)(g_cls + (long)(b * NCLS + row) * D_ + d0 + c4);
        }
        __syncthreads();
#pragma unroll
        for (int i = 0; i < 5; i++) {
            int p = i * 256 + tid;
            if (p < 64 * NCLS) {
                int tok = p / NCLS, c = p % NCLS;
                float s = acc[i];
#pragma unroll 8
                for (int d = 0; d < 128; d++)
                    s = fmaf(pt[tok][d], cs[c][d], s);
                acc[i] = s;
            }
        }
        __syncthreads();
    }
#pragma unroll
    for (int i = 0; i < 5; i++) {
        int p = i * 256 + tid;
        if (p < 64 * NCLS) sm_m[p / NCLS][p % NCLS] = acc[i];
    }
    __syncthreads();

    if (tid < 64) {
        const int n = t0 + tid;
        float mean = 0.f;
#pragma unroll
        for (int c = 0; c < NCLS; c++) mean += sm_m[tid][c];
        mean *= (1.f / (float)NCLS);
        float var = 0.f;
#pragma unroll
        for (int c = 0; c < NCLS; c++) {
            float d = sm_m[tid][c] - mean;
            var += d * d;
        }
        var *= (1.f / (float)NCLS);
        float inv = rsqrtf(var + 1e-5f);
        const int gy = n >> 5, gx = n & 31;
#pragma unroll
        for (int c = 0; c < NCLS; c++)
            g_mln[(((long)b * NCLS + c) * GS + gy) * GS + gx] =
                (sm_m[tid][c] - mean) * inv * mg[c] + mb[c];
    }
}

// ---------------- bilinear 32x32 -> 512x512 ---------------------------------
__global__ void __launch_bounds__(256) resize_kernel(float* __restrict__ out)
{
    const int pix = blockIdx.x * 256 + threadIdx.x;
    const int c = blockIdx.y, b = blockIdx.z;
    const int ox = pix & 511, oy = pix >> 9;
    float fx = (ox + 0.5f) * 0.0625f - 0.5f;
    float fy = (oy + 0.5f) * 0.0625f - 0.5f;
    int ix0 = (int)floorf(fx), iy0 = (int)floorf(fy);
    float wx = fx - (float)ix0, wy = fy - (float)iy0;
    int x0 = max(ix0, 0), x1 = min(ix0 + 1, GS - 1);
    int y0 = max(iy0, 0), y1 = min(iy0 + 1, GS - 1);
    const float* m = g_mln + ((long)b * NCLS + c) * GS * GS;
    float v00 = m[y0 * GS + x0], v01 = m[y0 * GS + x1];
    float v10 = m[y1 * GS + x0], v11 = m[y1 * GS + x1];
    float v = (1.f - wy) * ((1.f - wx) * v00 + wx * v01)
            +        wy  * ((1.f - wx) * v10 + wx * v11);
    out[(((long)b * NCLS + c) * IMG + oy) * IMG + ox] = v;
}

// ---------------- host orchestration ----------------------------------------
static void* sym_addr(const void* sym)
{
    void* p = nullptr;
    cudaGetSymbolAddress(&p, sym);
    return p;
}

#define SMEM_QKV  ((128 * 40 + 64 * 40) * 2 * 4)    // 61440

extern "C" void kernel_launch(void* const* d_in, const int* in_sizes, int n_in,
                              void* d_out, int out_size)
{
    (void)in_sizes; (void)n_in; (void)out_size;
    const float* x    = (const float*)d_in[0];
    const float* pdW  = (const float*)d_in[1];
    const float* pdb  = (const float*)d_in[2];
    const float* cls  = (const float*)d_in[3];
    const float* l1g  = (const float*)d_in[4];
    const float* l1b  = (const float*)d_in[5];
    const float* qW   = (const float*)d_in[6];
    const float* qb   = (const float*)d_in[7];
    const float* kW   = (const float*)d_in[8];
    const float* kb   = (const float*)d_in[9];
    const float* vW   = (const float*)d_in[10];
    const float* vb   = (const float*)d_in[11];
    const float* l2g  = (const float*)d_in[12];
    const float* l2b  = (const float*)d_in[13];
    const float* w1   = (const float*)d_in[14];
    const float* b1   = (const float*)d_in[15];
    const float* w2   = (const float*)d_in[16];
    const float* b2   = (const float*)d_in[17];
    const float* ppW  = (const float*)d_in[18];
    const float* pcW  = (const float*)d_in[19];
    const float* dg   = (const float*)d_in[20];
    const float* db   = (const float*)d_in[21];
    const float* mg   = (const float*)d_in[22];
    const float* mb   = (const float*)d_in[23];
    float* out = (float*)d_out;

    float*  gx   = (float*)sym_addr(g_x);
    __half* ghh  = (__half*)sym_addr(g_hh);
    __half* gff  = (__half*)sym_addr(g_ff);
    float*  gpt  = (float*)sym_addr(g_patches);
    float*  gcl  = (float*)sym_addr(g_cls);
    __half* wt   = (__half*)sym_addr(g_wt);
    __half* wqkv = (__half*)sym_addr(g_wqkv);

    cudaFuncSetAttribute(hgemm,
                         cudaFuncAttributeMaxDynamicSharedMemorySize, SMEM_H128);
    cudaFuncSetAttribute(qkv_gemm,
                         cudaFuncAttributeMaxDynamicSharedMemorySize, SMEM_QKV);
    cudaFuncSetAttribute(fattn_kernel,
                         cudaFuncAttributeMaxDynamicSharedMemorySize, FA_SMEM);

    const dim3 blk(256);
    const dim3 tsb(32, 8);
    const int mtiles = (M_ + 127) / 128;      // 66

    // ---- one-shot prep: weight transposes; x->half + cls broadcast ----
    prep_kernel<<<11232, tsb>>>(w1, w2, pdW, ppW, pcW, qW, kW, vW);
    cvtx_kernel<<<CVTX_BLKS + (NCLS * D_ + 255) / 256, 256>>>(x, cls);

    // ---- x(half) @ proj_dec + b -> g_x patch rows ----
    hgemm<<<dim3(6, 8, B_), blk, SMEM_H128>>>(
        ghh, wt + OFF_PD, pdb, gx,
        NPATCH, D_, D_, D_, D_, D_,
        1, (long)NPATCH * D_, 0, 0, 0, (long)S_ * D_, 0, 1);

    for (int l = 0; l < 2; l++) {
        ln_kernel<<<M_ / 8, blk>>>(gx, l1g + l * D_, l1b + l * D_, ghh);

        qkv_gemm<<<dim3(1, mtiles, 36), blk, SMEM_QKV>>>(
            ghh, wqkv + (long)l * 36 * 4096,
            qb + (long)l * NH * DH, kb + (long)l * NH * DH, vb + (long)l * NH * DH);

        fattn_kernel<<<dim3((S_ + 127) / 128, BHD), blk, FA_SMEM>>>();

        ln_kernel<<<M_ / 8, blk>>>(gx, l2g + l * D_, l2b + l * D_, ghh);

        hgemm<<<dim3(FF / 128, mtiles, 1), blk, SMEM_H128>>>(
            ghh, wt + (l ? OFF_W1_1 : OFF_W1_0), b1 + (long)l * FF, gff,
            M_, FF, D_, D_, D_, FF,
            1, 0, 0, 0, 0, 0, 0, 1 | 2 | 16);
        hgemm<<<dim3(D_ / 128, mtiles, 1), blk, SMEM_H128>>>(
            gff, wt + (l ? OFF_W2_1 : OFF_W2_0), b2 + (long)l * D_, gx,
            M_, D_, FF, FF, FF, D_,
            1, 0, 0, 0, 0, 0, 0, 1 | 4);
    }

    ln_kernel<<<M_ / 8, blk>>>(gx, dg, db, ghh);

    hgemm<<<dim3(6, 8, B_), blk, SMEM_H128>>>(
        ghh, wt + OFF_PP, nullptr, gpt,
        NPATCH, D_, D_, D_, D_, D_,
        1, (long)S_ * D_, 0, 0, 0, (long)NPATCH * D_, 0, 0);
    hgemm<<<dim3(6, 1, B_), blk, SMEM_H128>>>(
        ghh + (long)NPATCH * D_, wt + OFF_PC, nullptr, gcl,
        NCLS, D_, D_, D_, D_, D_,
        1, (long)S_ * D_, 0, 0, 0, (long)NCLS * D_, 0, 0);

    l2norm_kernel<<<1024 + NCLS, blk>>>();

    masks_kernel<<<dim3(NPATCH / 64, B_), blk>>>(mg, mb);
    resize_kernel<<<dim3(IMG * IMG / 256, NCLS, B_), blk>>>(out);
}